// round 1
// baseline (speedup 1.0000x reference)
#include <cuda_runtime.h>
#include <math.h>
#include <stdint.h>

#define NE   1024
#define NH   16
#define NKV  4
#define HD   64
#define SMAX 2048
#define BMAX 2
#define MMAX (BMAX*SMAX)

// ---------------- scratch (device globals; no allocation allowed) ----------
__device__ float g_qkv[MMAX * 1536];              // raw q|k|v per token
__device__ float g_q[(size_t)BMAX*NH*SMAX*HD];    // [b,h,s,d]
__device__ float g_k[(size_t)BMAX*NKV*SMAX*HD];   // [b,kh,s,d]
__device__ float g_v[(size_t)BMAX*NKV*SMAX*HD];   // [b,kh,s,d]
__device__ float g_y[(size_t)MMAX*NE];            // attention out, token-major

// ---------------- generic fp32 GEMM: C[m, coff+n] = sum_k A[m,k] * W[n,k] ---
// Tiles: BM=BN=64, BK=16, 256 threads, 4x4 microtile per thread.
__global__ void __launch_bounds__(256) gemm_abt(
    const float* __restrict__ A, const float* __restrict__ W,
    float* __restrict__ C, int K, int ldc, int coff)
{
    __shared__ float As[16][64];
    __shared__ float Bs[16][64];
    const int bm = blockIdx.y * 64;
    const int bn = blockIdx.x * 64;
    const int tid = threadIdx.x;
    const int tx = tid & 15, ty = tid >> 4;
    const int lr = tid >> 2;          // 0..63 row within tile
    const int lc = (tid & 3) << 2;    // 0,4,8,12 k offset
    const float* Ag = A + (size_t)(bm + lr) * K + lc;
    const float* Wg = W + (size_t)(bn + lr) * K + lc;

    float acc[4][4] = {};
    for (int k0 = 0; k0 < K; k0 += 16) {
        float4 av = *(const float4*)(Ag + k0);
        float4 wv = *(const float4*)(Wg + k0);
        As[lc+0][lr]=av.x; As[lc+1][lr]=av.y; As[lc+2][lr]=av.z; As[lc+3][lr]=av.w;
        Bs[lc+0][lr]=wv.x; Bs[lc+1][lr]=wv.y; Bs[lc+2][lr]=wv.z; Bs[lc+3][lr]=wv.w;
        __syncthreads();
        #pragma unroll
        for (int kk = 0; kk < 16; kk++) {
            float4 a4 = *(const float4*)&As[kk][ty*4];
            float4 b4 = *(const float4*)&Bs[kk][tx*4];
            float a[4] = {a4.x, a4.y, a4.z, a4.w};
            float b[4] = {b4.x, b4.y, b4.z, b4.w};
            #pragma unroll
            for (int i = 0; i < 4; i++)
                #pragma unroll
                for (int j = 0; j < 4; j++)
                    acc[i][j] = fmaf(a[i], b[j], acc[i][j]);
        }
        __syncthreads();
    }
    #pragma unroll
    for (int i = 0; i < 4; i++) {
        float* Cr = C + (size_t)(bm + ty*4 + i) * ldc + coff + bn + tx*4;
        #pragma unroll
        for (int j = 0; j < 4; j++) Cr[j] = acc[i][j];
    }
}

// ---------------- rope + rmsnorm + ve-gate ---------------------------------
// One block (128 thr = 4 warps) per token. Warp w: q heads 4w..4w+3, kv head w.
__global__ void __launch_bounds__(128) rope_kernel(
    const float* __restrict__ x, const float* __restrict__ ve,
    const float* __restrict__ cosb, const float* __restrict__ sinb,
    const float* __restrict__ Wgate, int S)
{
    const int m = blockIdx.x;
    const int b = m / S, s = m - b * S;
    const int warp = threadIdx.x >> 5, lane = threadIdx.x & 31;
    const float c  = cosb[s*32 + lane];
    const float sn = sinb[s*32 + lane];
    const float* row = g_qkv + (size_t)m * 1536;

    // q heads
    #pragma unroll
    for (int hh = 0; hh < 4; hh++) {
        int h = warp * 4 + hh;
        float t1 = row[h*64 + lane];
        float t2 = row[h*64 + 32 + lane];
        float r1 = t1*c + t2*sn;
        float r2 = t2*c - t1*sn;
        float ss = r1*r1 + r2*r2;
        #pragma unroll
        for (int o = 16; o; o >>= 1) ss += __shfl_xor_sync(0xffffffffu, ss, o);
        float inv = rsqrtf(ss * (1.0f/64.0f) + 1.1920929e-07f) * 1.2f;
        float* dst = g_q + ((size_t)(b*NH + h)*S + s) * HD;
        dst[lane]      = r1 * inv;
        dst[lane + 32] = r2 * inv;
    }
    // k head (warp -> kv head) + v with gate
    {
        int h = warp;
        float t1 = row[1024 + h*64 + lane];
        float t2 = row[1024 + h*64 + 32 + lane];
        float r1 = t1*c + t2*sn;
        float r2 = t2*c - t1*sn;
        float ss = r1*r1 + r2*r2;
        #pragma unroll
        for (int o = 16; o; o >>= 1) ss += __shfl_xor_sync(0xffffffffu, ss, o);
        float inv = rsqrtf(ss * (1.0f/64.0f) + 1.1920929e-07f) * 1.2f;
        float* kdst = g_k + ((size_t)(b*NKV + h)*S + s) * HD;
        kdst[lane]      = r1 * inv;
        kdst[lane + 32] = r2 * inv;

        float gz = (lane < 12) ? x[(size_t)m*NE + lane] * Wgate[h*12 + lane] : 0.f;
        #pragma unroll
        for (int o = 16; o; o >>= 1) gz += __shfl_xor_sync(0xffffffffu, gz, o);
        float gate = 3.0f / (1.0f + __expf(-gz));
        float v1 = row[1280 + h*64 + lane]      + gate * ve[(size_t)m*256 + h*64 + lane];
        float v2 = row[1280 + h*64 + 32 + lane] + gate * ve[(size_t)m*256 + h*64 + 32 + lane];
        float* vdst = g_v + ((size_t)(b*NKV + h)*S + s) * HD;
        vdst[lane]      = v1;
        vdst[lane + 32] = v2;
    }
}

// ---------------- windowed flash attention ---------------------------------
// Block = 256 thr (8 warps). Q tile 64 rows; warp owns 8 rows; lane owns
// cols/dims {lane, lane+32}. K stored transposed in smem for conflict-free
// score reads; P aliases the K^T region after a syncthreads.
__global__ void __launch_bounds__(256) attn_kernel(
    const int* __restrict__ amask, const int* __restrict__ lwp, int S)
{
    extern __shared__ float sm[];
    float* sQ  = sm;                 // [64][64]
    float* sKT = sm + 64*64;         // [64][68] (d-major), later aliased as P[64][68]
    float* sV  = sKT + 64*68;        // [64][64]

    const int q0 = blockIdx.x * 64;
    const int h  = blockIdx.y;
    const int b  = blockIdx.z;
    const int kvh = h >> 2;
    const int LW = *lwp;
    const int tid = threadIdx.x, warp = tid >> 5, lane = tid & 31;

    const float* Qg  = g_q + ((size_t)(b*NH  + h  )*S + q0) * HD;
    const float* Kg0 = g_k + ((size_t)(b*NKV + kvh)*S) * HD;
    const float* Vg0 = g_v + ((size_t)(b*NKV + kvh)*S) * HD;

    for (int i = tid; i < 64*16; i += 256) {
        int r = i >> 4, c = (i & 15) << 2;
        *(float4*)&sQ[r*64 + c] = *(const float4*)&Qg[r*64 + c];
    }

    float m_i[8], l_i[8], acc[8][2];
    #pragma unroll
    for (int rr = 0; rr < 8; rr++) { m_i[rr] = -1e30f; l_i[rr] = 0.f; acc[rr][0] = 0.f; acc[rr][1] = 0.f; }

    int kmin = q0 - LW + 1; if (kmin < 0) kmin = 0;
    const int kt0 = kmin >> 6, kt1 = (q0 + 63) >> 6;

    for (int kt = kt0; kt <= kt1; kt++) {
        const int k0 = kt << 6;
        __syncthreads();  // prior iteration done with sKT(=P) and sV
        const float* Kg = Kg0 + (size_t)k0 * HD;
        const float* Vg = Vg0 + (size_t)k0 * HD;
        for (int i = tid; i < 64*16; i += 256) {
            int r = i >> 4, c = (i & 15) << 2;
            float4 kv = *(const float4*)&Kg[r*64 + c];
            sKT[(c+0)*68 + r] = kv.x; sKT[(c+1)*68 + r] = kv.y;
            sKT[(c+2)*68 + r] = kv.z; sKT[(c+3)*68 + r] = kv.w;
            *(float4*)&sV[r*64 + c] = *(const float4*)&Vg[r*64 + c];
        }
        __syncthreads();

        const int mka = amask[b*S + k0 + lane];
        const int mkb = amask[b*S + k0 + 32 + lane];

        float sc[8][2];
        #pragma unroll
        for (int rr = 0; rr < 8; rr++) { sc[rr][0] = 0.f; sc[rr][1] = 0.f; }
        #pragma unroll
        for (int d = 0; d < 64; d += 4) {
            float ka[4], kb[4];
            #pragma unroll
            for (int j = 0; j < 4; j++) {
                ka[j] = sKT[(d+j)*68 + lane];
                kb[j] = sKT[(d+j)*68 + 32 + lane];
            }
            #pragma unroll
            for (int rr = 0; rr < 8; rr++) {
                const float4 q4 = *(const float4*)&sQ[(warp*8 + rr)*64 + d];
                sc[rr][0] += q4.x*ka[0] + q4.y*ka[1] + q4.z*ka[2] + q4.w*ka[3];
                sc[rr][1] += q4.x*kb[0] + q4.y*kb[1] + q4.z*kb[2] + q4.w*kb[3];
            }
        }
        __syncthreads();  // everyone finished reading sKT -> safe to write P

        #pragma unroll
        for (int rr = 0; rr < 8; rr++) {
            const int q  = q0 + warp*8 + rr;
            const int ka_ = k0 + lane, kb_ = k0 + 32 + lane;
            const bool a0 = (ka_ <= q) && (q - ka_ < LW) && (mka != 0);
            const bool a1 = (kb_ <= q) && (q - kb_ < LW) && (mkb != 0);
            float s0 = a0 ? sc[rr][0] * 0.125f : -1e30f;
            float s1 = a1 ? sc[rr][1] * 0.125f : -1e30f;
            float mt = fmaxf(s0, s1);
            #pragma unroll
            for (int o = 16; o; o >>= 1) mt = fmaxf(mt, __shfl_xor_sync(0xffffffffu, mt, o));
            float mn = fmaxf(m_i[rr], mt);
            float alpha = __expf(m_i[rr] - mn);
            float p0 = (s0 <= -1e29f) ? 0.f : __expf(s0 - mn);
            float p1 = (s1 <= -1e29f) ? 0.f : __expf(s1 - mn);
            float rs = p0 + p1;
            #pragma unroll
            for (int o = 16; o; o >>= 1) rs += __shfl_xor_sync(0xffffffffu, rs, o);
            m_i[rr] = mn;
            l_i[rr] = l_i[rr]*alpha + rs;
            acc[rr][0] *= alpha; acc[rr][1] *= alpha;
            sKT[(warp*8 + rr)*68 + lane]      = p0;   // P alias
            sKT[(warp*8 + rr)*68 + 32 + lane] = p1;
        }
        __syncwarp();  // warp reads only its own P rows

        #pragma unroll
        for (int c0 = 0; c0 < 64; c0 += 4) {
            float va[4], vb[4];
            #pragma unroll
            for (int j = 0; j < 4; j++) {
                va[j] = sV[(c0+j)*64 + lane];
                vb[j] = sV[(c0+j)*64 + 32 + lane];
            }
            #pragma unroll
            for (int rr = 0; rr < 8; rr++) {
                const float4 p4 = *(const float4*)&sKT[(warp*8 + rr)*68 + c0];
                acc[rr][0] += p4.x*va[0] + p4.y*va[1] + p4.z*va[2] + p4.w*va[3];
                acc[rr][1] += p4.x*vb[0] + p4.y*vb[1] + p4.z*vb[2] + p4.w*vb[3];
            }
        }
    }

    #pragma unroll
    for (int rr = 0; rr < 8; rr++) {
        const int row = warp*8 + rr;
        const float inv = 1.0f / l_i[rr];
        float* yo = g_y + (size_t)(b*S + q0 + row) * NE + h*HD;
        yo[lane]      = acc[rr][0] * inv;
        yo[lane + 32] = acc[rr][1] * inv;
    }
}

// ---------------- launch ----------------------------------------------------
extern "C" void kernel_launch(void* const* d_in, const int* in_sizes, int n_in,
                              void* d_out, int out_size)
{
    const float* x     = (const float*)d_in[0];
    const float* ve    = (const float*)d_in[1];
    const float* cosb  = (const float*)d_in[2];
    const float* sinb  = (const float*)d_in[3];
    const float* Wq    = (const float*)d_in[4];
    const float* Wk    = (const float*)d_in[5];
    const float* Wv    = (const float*)d_in[6];
    const float* Wproj = (const float*)d_in[7];
    const float* Wgate = (const float*)d_in[8];
    const int*   amask = (const int*)d_in[9];
    const int*   lw    = (const int*)d_in[10];
    float* out = (float*)d_out;

    const int S = in_sizes[2] / 32;        // cos is (S,1,32)
    const int B = in_sizes[0] / (S * NE);
    const int M = B * S;

    float *qkv_p, *y_p;
    cudaGetSymbolAddress((void**)&qkv_p, g_qkv);
    cudaGetSymbolAddress((void**)&y_p,  g_y);

    // QKV projections into fused [M, 1536] buffer
    gemm_abt<<<dim3(NE/64,  M/64), 256>>>(x, Wq, qkv_p, NE, 1536, 0);
    gemm_abt<<<dim3(256/64, M/64), 256>>>(x, Wk, qkv_p, NE, 1536, 1024);
    gemm_abt<<<dim3(256/64, M/64), 256>>>(x, Wv, qkv_p, NE, 1536, 1280);

    // rope + rmsnorm + gate
    rope_kernel<<<M, 128>>>(x, ve, cosb, sinb, Wgate, S);

    // attention
    const size_t smem = (size_t)(64*64 + 64*68 + 64*64) * sizeof(float); // 50176 B
    cudaFuncSetAttribute(attn_kernel, cudaFuncAttributeMaxDynamicSharedMemorySize, (int)smem);
    attn_kernel<<<dim3(S/64, NH, B), 256, smem>>>(amask, lw, S);

    // output projection
    gemm_abt<<<dim3(NE/64, M/64), 256>>>(y_p, Wproj, out, NE, NE, 0);
}

// round 3
// speedup vs baseline: 1.9320x; 1.9320x over previous
#include <cuda_runtime.h>
#include <cuda_bf16.h>
#include <math.h>
#include <stdint.h>

#define NE   1024
#define NH   16
#define NKV  4
#define HD   64
#define SMAX 2048
#define BMAX 2
#define MMAX (BMAX*SMAX)

typedef unsigned long long ull;

// ---------------- scratch (device globals; no allocation allowed) ----------
__device__ float g_qkv[MMAX * 1536];                  // raw q|k|v per token (fp32)
__device__ float g_q[(size_t)BMAX*NH*SMAX*HD];        // [b,h,s,d]
__device__ float g_k[(size_t)BMAX*NKV*SMAX*HD];       // [b,kh,s,d]
__device__ float g_v[(size_t)BMAX*NKV*SMAX*HD];       // [b,kh,s,d]
__device__ __nv_bfloat16 g_xh[(size_t)MMAX*NE];       // x hi/lo split
__device__ __nv_bfloat16 g_xl[(size_t)MMAX*NE];
__device__ __nv_bfloat16 g_wh[1536*1024];             // fused Wq|Wk|Wv hi/lo
__device__ __nv_bfloat16 g_wl[1536*1024];
__device__ __nv_bfloat16 g_wph[1024*1024];            // Wproj hi/lo
__device__ __nv_bfloat16 g_wpl[1024*1024];
__device__ __nv_bfloat16 g_yh[(size_t)MMAX*NE];       // attention out hi/lo
__device__ __nv_bfloat16 g_yl[(size_t)MMAX*NE];

// ---------------- PTX helpers (family-generic only!) ------------------------
__device__ __forceinline__ uint32_t smem_to_u32(const void* p) {
    uint32_t a;
    asm("{ .reg .u64 t; cvta.to.shared.u64 t, %1; cvt.u32.u64 %0, t; }" : "=r"(a) : "l"(p));
    return a;
}
__device__ __forceinline__ void ldsm_x4(uint32_t& r0, uint32_t& r1, uint32_t& r2,
                                        uint32_t& r3, uint32_t addr) {
    asm volatile("ldmatrix.sync.aligned.m8n8.x4.shared.b16 {%0,%1,%2,%3}, [%4];"
        : "=r"(r0), "=r"(r1), "=r"(r2), "=r"(r3) : "r"(addr));
}
__device__ __forceinline__ void mma_bf16(float* c, const uint32_t* a, const uint32_t* b) {
    asm volatile("mma.sync.aligned.m16n8k16.row.col.f32.bf16.bf16.f32 "
        "{%0,%1,%2,%3}, {%4,%5,%6,%7}, {%8,%9}, {%0,%1,%2,%3};"
        : "+f"(c[0]), "+f"(c[1]), "+f"(c[2]), "+f"(c[3])
        : "r"(a[0]), "r"(a[1]), "r"(a[2]), "r"(a[3]), "r"(b[0]), "r"(b[1]));
}
__device__ __forceinline__ void cp16(uint32_t dst, const void* src) {
    asm volatile("cp.async.cg.shared.global [%0], [%1], 16;" :: "r"(dst), "l"(src));
}
#define CP_COMMIT() asm volatile("cp.async.commit_group;" ::: "memory")
#define CP_WAIT(n)  asm volatile("cp.async.wait_group %0;" :: "n"(n) : "memory")

// packed fp32 pair helpers
union F2U { ull u; float2 f; };
__device__ __forceinline__ void ffma2(ull& d, ull a, ull b) {
    asm("fma.rn.f32x2 %0, %1, %2, %0;" : "+l"(d) : "l"(a), "l"(b));
}
__device__ __forceinline__ ull mul2(ull a, ull b) {
    ull r; asm("mul.rn.f32x2 %0, %1, %2;" : "=l"(r) : "l"(a), "l"(b)); return r;
}
__device__ __forceinline__ ull pack2(float x, float y) {
    ull r; asm("mov.b64 %0, {%1, %2};" : "=l"(r) : "f"(x), "f"(y)); return r;
}

// ---------------- fp32 -> bf16 hi/lo split ----------------------------------
__global__ void __launch_bounds__(256) cvt_split(
    const float* __restrict__ in, __nv_bfloat16* __restrict__ h,
    __nv_bfloat16* __restrict__ l, int n4)
{
    int i = blockIdx.x * 256 + threadIdx.x;
    if (i >= n4) return;
    float4 v = ((const float4*)in)[i];
    __nv_bfloat16 h0 = __float2bfloat16(v.x), h1 = __float2bfloat16(v.y);
    __nv_bfloat16 h2 = __float2bfloat16(v.z), h3 = __float2bfloat16(v.w);
    __nv_bfloat162* hp = (__nv_bfloat162*)h;
    hp[i*2]   = __nv_bfloat162(h0, h1);
    hp[i*2+1] = __nv_bfloat162(h2, h3);
    __nv_bfloat162* lp = (__nv_bfloat162*)l;
    lp[i*2]   = __nv_bfloat162(__float2bfloat16(v.x - __bfloat162float(h0)),
                               __float2bfloat16(v.y - __bfloat162float(h1)));
    lp[i*2+1] = __nv_bfloat162(__float2bfloat16(v.z - __bfloat162float(h2)),
                               __float2bfloat16(v.w - __bfloat162float(h3)));
}

// ---------------- mma.sync bf16-split GEMM ----------------------------------
// C[bm..+127, bn..+127] = A[M,K] * W[N,K]^T, A ~ Ah+Al, W ~ Wh+Wl (3 MMAs).
// 256 thr, warp tile 32x64, BK=64, 3-stage cp.async pipeline, SW128 swizzle.
#define STG_BYTES 65536   /* Ah|Al|Bh|Bl regions, 16KB each */
#define GSMEM (3*STG_BYTES)

__device__ __forceinline__ void gemm_issue_stage(
    uint32_t sbase, int stg, int kc,
    const __nv_bfloat16* __restrict__ Ah, const __nv_bfloat16* __restrict__ Al,
    const __nv_bfloat16* __restrict__ Wh, const __nv_bfloat16* __restrict__ Wl,
    int bm, int bn, int K, int tid)
{
    #pragma unroll
    for (int i = 0; i < 16; i++) {
        const int idx = i * 256 + tid;           // 0..4095
        const int region = idx >> 10;            // 0:Ah 1:Al 2:Bh 3:Bl
        const int cid = idx & 1023;
        const int row = cid >> 3, c16 = cid & 7;
        const uint32_t off = row * 128 + c16 * 16;
        const uint32_t sw = off ^ ((off >> 3) & 0x70);
        const int gk = kc * 64 + c16 * 8;
        const __nv_bfloat16* src;
        if      (region == 0) src = Ah + (size_t)(bm + row) * K + gk;
        else if (region == 1) src = Al + (size_t)(bm + row) * K + gk;
        else if (region == 2) src = Wh + (size_t)(bn + row) * K + gk;
        else                  src = Wl + (size_t)(bn + row) * K + gk;
        cp16(sbase + stg * STG_BYTES + region * 16384 + sw, src);
    }
}

__global__ void __launch_bounds__(256, 1) gemm_mma(
    const __nv_bfloat16* __restrict__ Ah, const __nv_bfloat16* __restrict__ Al,
    const __nv_bfloat16* __restrict__ Wh, const __nv_bfloat16* __restrict__ Wl,
    float* __restrict__ C, int ldc)
{
    constexpr int K = 1024;
    constexpr int NK = K / 64;
    extern __shared__ char gsm[];
    const uint32_t sbase = smem_to_u32(gsm);
    const int tid = threadIdx.x, wid = tid >> 5, lane = tid & 31;
    const int warpM = wid & 3, warpN = wid >> 2;      // 4 x 2 warps
    const int bm = blockIdx.y * 128, bn = blockIdx.x * 128;

    float c[2][8][4];
    #pragma unroll
    for (int mt = 0; mt < 2; mt++)
        #pragma unroll
        for (int n = 0; n < 8; n++)
            #pragma unroll
            for (int j = 0; j < 4; j++) c[mt][n][j] = 0.f;

    // ldmatrix lane-address components
    const int rIn = lane & 7, mId = lane >> 3;

    gemm_issue_stage(sbase, 0, 0, Ah, Al, Wh, Wl, bm, bn, K, tid); CP_COMMIT();
    gemm_issue_stage(sbase, 1, 1, Ah, Al, Wh, Wl, bm, bn, K, tid); CP_COMMIT();

    for (int kc = 0; kc < NK; kc++) {
        const int stg = kc % 3;
        if (kc + 2 < NK) {
            gemm_issue_stage(sbase, (kc + 2) % 3, kc + 2, Ah, Al, Wh, Wl, bm, bn, K, tid);
            CP_COMMIT();
            CP_WAIT(2);
        } else if (kc + 1 < NK) {
            CP_WAIT(1);
        } else {
            CP_WAIT(0);
        }
        __syncthreads();

        const uint32_t aAh = sbase + stg * STG_BYTES;
        const uint32_t aAl = aAh + 16384;
        const uint32_t aBh = aAl + 16384;
        const uint32_t aBl = aBh + 16384;

        #pragma unroll
        for (int kk = 0; kk < 64; kk += 16) {
            uint32_t ah[2][4], al[2][4];
            #pragma unroll
            for (int mt = 0; mt < 2; mt++) {
                const int row = warpM * 32 + mt * 16 + (mId & 1) * 8 + rIn;
                const int colB = (kk + (mId >> 1) * 8) * 2;
                const uint32_t off = row * 128 + colB;
                const uint32_t sw = off ^ ((off >> 3) & 0x70);
                ldsm_x4(ah[mt][0], ah[mt][1], ah[mt][2], ah[mt][3], aAh + sw);
                ldsm_x4(al[mt][0], al[mt][1], al[mt][2], al[mt][3], aAl + sw);
            }
            uint32_t bh[8][2], bl[8][2];
            #pragma unroll
            for (int nt = 0; nt < 4; nt++) {
                const int row = warpN * 64 + nt * 16 + (mId >> 1) * 8 + rIn;
                const int colB = (kk + (mId & 1) * 8) * 2;
                const uint32_t off = row * 128 + colB;
                const uint32_t sw = off ^ ((off >> 3) & 0x70);
                ldsm_x4(bh[2*nt][0], bh[2*nt][1], bh[2*nt+1][0], bh[2*nt+1][1], aBh + sw);
                ldsm_x4(bl[2*nt][0], bl[2*nt][1], bl[2*nt+1][0], bl[2*nt+1][1], aBl + sw);
            }
            #pragma unroll
            for (int mt = 0; mt < 2; mt++)
                #pragma unroll
                for (int n = 0; n < 8; n++) {
                    mma_bf16(c[mt][n], ah[mt], bh[n]);
                    mma_bf16(c[mt][n], ah[mt], bl[n]);
                    mma_bf16(c[mt][n], al[mt], bh[n]);
                }
        }
        __syncthreads();
    }

    // epilogue
    const int g = lane >> 2, t = lane & 3;
    #pragma unroll
    for (int mt = 0; mt < 2; mt++) {
        #pragma unroll
        for (int n = 0; n < 8; n++) {
            const int r0 = bm + warpM * 32 + mt * 16 + g;
            const int col = bn + warpN * 64 + n * 8 + t * 2;
            *(float2*)&C[(size_t)r0 * ldc + col]       = make_float2(c[mt][n][0], c[mt][n][1]);
            *(float2*)&C[(size_t)(r0 + 8) * ldc + col] = make_float2(c[mt][n][2], c[mt][n][3]);
        }
    }
}

// ---------------- rope + rmsnorm + ve-gate ---------------------------------
__global__ void __launch_bounds__(128) rope_kernel(
    const float* __restrict__ x, const float* __restrict__ ve,
    const float* __restrict__ cosb, const float* __restrict__ sinb,
    const float* __restrict__ Wgate, int S)
{
    const int m = blockIdx.x;
    const int b = m / S, s = m - b * S;
    const int warp = threadIdx.x >> 5, lane = threadIdx.x & 31;
    const float c  = cosb[s*32 + lane];
    const float sn = sinb[s*32 + lane];
    const float* row = g_qkv + (size_t)m * 1536;

    #pragma unroll
    for (int hh = 0; hh < 4; hh++) {
        int h = warp * 4 + hh;
        float t1 = row[h*64 + lane];
        float t2 = row[h*64 + 32 + lane];
        float r1 = t1*c + t2*sn;
        float r2 = t2*c - t1*sn;
        float ss = r1*r1 + r2*r2;
        #pragma unroll
        for (int o = 16; o; o >>= 1) ss += __shfl_xor_sync(0xffffffffu, ss, o);
        float inv = rsqrtf(ss * (1.0f/64.0f) + 1.1920929e-07f) * 1.2f;
        float* dst = g_q + ((size_t)(b*NH + h)*S + s) * HD;
        dst[lane]      = r1 * inv;
        dst[lane + 32] = r2 * inv;
    }
    {
        int h = warp;
        float t1 = row[1024 + h*64 + lane];
        float t2 = row[1024 + h*64 + 32 + lane];
        float r1 = t1*c + t2*sn;
        float r2 = t2*c - t1*sn;
        float ss = r1*r1 + r2*r2;
        #pragma unroll
        for (int o = 16; o; o >>= 1) ss += __shfl_xor_sync(0xffffffffu, ss, o);
        float inv = rsqrtf(ss * (1.0f/64.0f) + 1.1920929e-07f) * 1.2f;
        float* kdst = g_k + ((size_t)(b*NKV + h)*S + s) * HD;
        kdst[lane]      = r1 * inv;
        kdst[lane + 32] = r2 * inv;

        float gz = (lane < 12) ? x[(size_t)m*NE + lane] * Wgate[h*12 + lane] : 0.f;
        #pragma unroll
        for (int o = 16; o; o >>= 1) gz += __shfl_xor_sync(0xffffffffu, gz, o);
        float gate = 3.0f / (1.0f + __expf(-gz));
        float v1 = row[1280 + h*64 + lane]      + gate * ve[(size_t)m*256 + h*64 + lane];
        float v2 = row[1280 + h*64 + 32 + lane] + gate * ve[(size_t)m*256 + h*64 + 32 + lane];
        float* vdst = g_v + ((size_t)(b*NKV + h)*S + s) * HD;
        vdst[lane]      = v1;
        vdst[lane + 32] = v2;
    }
}

// ---------------- windowed flash attention (packed f32x2) -------------------
__global__ void __launch_bounds__(256) attn_kernel(
    const int* __restrict__ amask, const int* __restrict__ lwp, int S)
{
    extern __shared__ float sm[];
    float* sQ  = sm;              // [64][64]
    float* sK  = sm + 4096;       // [64 key][66]
    float* sVT = sm + 4096+4224;  // [64 dim][66]
    float* sP  = sm + 4096+8448;  // [64 row][66]

    const int q0 = blockIdx.x * 64;
    const int h  = blockIdx.y;
    const int bz = blockIdx.z;
    const int kvh = h >> 2;
    const int LW = *lwp;
    const int tid = threadIdx.x, warp = tid >> 5, lane = tid & 31;

    const float* Qg  = g_q + ((size_t)(bz*NH  + h  )*S + q0) * HD;
    const float* Kg0 = g_k + ((size_t)(bz*NKV + kvh)*S) * HD;
    const float* Vg0 = g_v + ((size_t)(bz*NKV + kvh)*S) * HD;

    for (int i = tid; i < 64*16; i += 256) {
        int r = i >> 4, c = (i & 15) << 2;
        *(float4*)&sQ[r*64 + c] = *(const float4*)&Qg[r*64 + c];
    }

    float m_i[8], l_i[8];
    ull acc_a[8], acc_b[8];
    #pragma unroll
    for (int rr = 0; rr < 8; rr++) { m_i[rr] = -1e30f; l_i[rr] = 0.f; acc_a[rr] = 0ull; acc_b[rr] = 0ull; }

    int kmin = q0 - LW + 1; if (kmin < 0) kmin = 0;
    const int kt0 = kmin >> 6, kt1 = q0 >> 6;

    for (int kt = kt0; kt <= kt1; kt++) {
        const int k0 = kt << 6;
        __syncthreads();
        const float* Kg = Kg0 + (size_t)k0 * HD;
        const float* Vg = Vg0 + (size_t)k0 * HD;
        for (int i = tid; i < 64*16; i += 256) {
            int r = i >> 4, c = (i & 15) << 2;
            float4 kv = *(const float4*)&Kg[r*64 + c];
            float2* kd = (float2*)&sK[r*66 + c];
            kd[0] = make_float2(kv.x, kv.y);
            kd[1] = make_float2(kv.z, kv.w);
            float4 vv = *(const float4*)&Vg[r*64 + c];
            sVT[(c+0)*66 + r] = vv.x;
            sVT[(c+1)*66 + r] = vv.y;
            sVT[(c+2)*66 + r] = vv.z;
            sVT[(c+3)*66 + r] = vv.w;
        }
        __syncthreads();

        const int mka = amask[bz*S + k0 + lane];
        const int mkb = amask[bz*S + k0 + 32 + lane];

        ull sa2[8], sb2[8];
        #pragma unroll
        for (int rr = 0; rr < 8; rr++) { sa2[rr] = 0ull; sb2[rr] = 0ull; }
        #pragma unroll
        for (int d = 0; d < 64; d += 4) {
            ull ka0 = *(const ull*)&sK[lane*66 + d];
            ull ka1 = *(const ull*)&sK[lane*66 + d + 2];
            ull kb0 = *(const ull*)&sK[(lane+32)*66 + d];
            ull kb1 = *(const ull*)&sK[(lane+32)*66 + d + 2];
            #pragma unroll
            for (int rr = 0; rr < 8; rr++) {
                const ull* qp = (const ull*)&sQ[(warp*8 + rr)*64 + d];
                ull q0v = qp[0], q1v = qp[1];
                ffma2(sa2[rr], q0v, ka0); ffma2(sa2[rr], q1v, ka1);
                ffma2(sb2[rr], q0v, kb0); ffma2(sb2[rr], q1v, kb1);
            }
        }

        #pragma unroll
        for (int rr = 0; rr < 8; rr++) {
            F2U fa; fa.u = sa2[rr];
            F2U fb; fb.u = sb2[rr];
            float sc0 = fa.f.x + fa.f.y;
            float sc1 = fb.f.x + fb.f.y;
            const int qi  = q0 + warp*8 + rr;
            const int ka_ = k0 + lane, kb_ = k0 + 32 + lane;
            const bool a0 = (ka_ <= qi) && (qi - ka_ < LW) && (mka != 0);
            const bool a1 = (kb_ <= qi) && (qi - kb_ < LW) && (mkb != 0);
            float s0 = a0 ? sc0 * 0.125f : -1e30f;
            float s1 = a1 ? sc1 * 0.125f : -1e30f;
            float mt = fmaxf(s0, s1);
            #pragma unroll
            for (int o = 16; o; o >>= 1) mt = fmaxf(mt, __shfl_xor_sync(0xffffffffu, mt, o));
            float mn = fmaxf(m_i[rr], mt);
            float alpha = __expf(m_i[rr] - mn);
            float p0 = a0 ? __expf(s0 - mn) : 0.f;
            float p1 = a1 ? __expf(s1 - mn) : 0.f;
            float rs = p0 + p1;
            #pragma unroll
            for (int o = 16; o; o >>= 1) rs += __shfl_xor_sync(0xffffffffu, rs, o);
            m_i[rr] = mn;
            l_i[rr] = l_i[rr]*alpha + rs;
            ull al2 = pack2(alpha, alpha);
            acc_a[rr] = mul2(acc_a[rr], al2);
            acc_b[rr] = mul2(acc_b[rr], al2);
            sP[(warp*8 + rr)*66 + lane]      = p0;
            sP[(warp*8 + rr)*66 + 32 + lane] = p1;
        }
        __syncwarp();

        #pragma unroll
        for (int k = 0; k < 64; k += 4) {
            ull va0 = *(const ull*)&sVT[lane*66 + k];
            ull va1 = *(const ull*)&sVT[lane*66 + k + 2];
            ull vb0 = *(const ull*)&sVT[(lane+32)*66 + k];
            ull vb1 = *(const ull*)&sVT[(lane+32)*66 + k + 2];
            #pragma unroll
            for (int rr = 0; rr < 8; rr++) {
                const ull* pp = (const ull*)&sP[(warp*8 + rr)*66 + k];
                ull p0v = pp[0], p1v = pp[1];
                ffma2(acc_a[rr], p0v, va0); ffma2(acc_a[rr], p1v, va1);
                ffma2(acc_b[rr], p0v, vb0); ffma2(acc_b[rr], p1v, vb1);
            }
        }
    }

    #pragma unroll
    for (int rr = 0; rr < 8; rr++) {
        const int row = warp*8 + rr;
        const float inv = 1.0f / l_i[rr];
        F2U fa; fa.u = acc_a[rr];
        F2U fb; fb.u = acc_b[rr];
        float ya = (fa.f.x + fa.f.y) * inv;
        float yb = (fb.f.x + fb.f.y) * inv;
        size_t o = (size_t)(bz*S + q0 + row) * NE + h*HD;
        __nv_bfloat16 ha = __float2bfloat16(ya);
        __nv_bfloat16 hb = __float2bfloat16(yb);
        g_yh[o + lane]      = ha;
        g_yh[o + 32 + lane] = hb;
        g_yl[o + lane]      = __float2bfloat16(ya - __bfloat162float(ha));
        g_yl[o + 32 + lane] = __float2bfloat16(yb - __bfloat162float(hb));
    }
}

// ---------------- launch ----------------------------------------------------
extern "C" void kernel_launch(void* const* d_in, const int* in_sizes, int n_in,
                              void* d_out, int out_size)
{
    const float* x     = (const float*)d_in[0];
    const float* ve    = (const float*)d_in[1];
    const float* cosb  = (const float*)d_in[2];
    const float* sinb  = (const float*)d_in[3];
    const float* Wq    = (const float*)d_in[4];
    const float* Wk    = (const float*)d_in[5];
    const float* Wv    = (const float*)d_in[6];
    const float* Wproj = (const float*)d_in[7];
    const float* Wgate = (const float*)d_in[8];
    const int*   amask = (const int*)d_in[9];
    const int*   lw    = (const int*)d_in[10];
    float* out = (float*)d_out;

    const int S = in_sizes[2] / 32;        // cos is (S,1,32)
    const int B = in_sizes[0] / (S * NE);
    const int M = B * S;

    float *qkv_p;
    __nv_bfloat16 *xh, *xl, *wh, *wl, *wph, *wpl, *yh, *yl;
    cudaGetSymbolAddress((void**)&qkv_p, g_qkv);
    cudaGetSymbolAddress((void**)&xh, g_xh);
    cudaGetSymbolAddress((void**)&xl, g_xl);
    cudaGetSymbolAddress((void**)&wh, g_wh);
    cudaGetSymbolAddress((void**)&wl, g_wl);
    cudaGetSymbolAddress((void**)&wph, g_wph);
    cudaGetSymbolAddress((void**)&wpl, g_wpl);
    cudaGetSymbolAddress((void**)&yh, g_yh);
    cudaGetSymbolAddress((void**)&yl, g_yl);

    // fp32 -> bf16 hi/lo splits (x and weights; Wq|Wk|Wv fused row-wise)
    {
        int n4 = M * NE / 4;
        cvt_split<<<(n4 + 255)/256, 256>>>(x, xh, xl, n4);
        n4 = 1024*1024/4;
        cvt_split<<<(n4 + 255)/256, 256>>>(Wq, wh, wl, n4);
        cvt_split<<<(n4 + 255)/256, 256>>>(Wproj, wph, wpl, n4);
        n4 = 256*1024/4;
        cvt_split<<<(n4 + 255)/256, 256>>>(Wk, wh + 1024*1024, wl + 1024*1024, n4);
        cvt_split<<<(n4 + 255)/256, 256>>>(Wv, wh + 1280*1024, wl + 1280*1024, n4);
    }

    cudaFuncSetAttribute(gemm_mma, cudaFuncAttributeMaxDynamicSharedMemorySize, GSMEM);

    // fused QKV projection: [M,1536] = x @ [Wq|Wk|Wv]^T
    gemm_mma<<<dim3(12, M/128), 256, GSMEM>>>(xh, xl, wh, wl, qkv_p, 1536);

    // rope + rmsnorm + gate
    rope_kernel<<<M, 128>>>(x, ve, cosb, sinb, Wgate, S);

    // attention
    const size_t asmem = (size_t)(4096 + 3*4224) * sizeof(float); // 67072 B
    cudaFuncSetAttribute(attn_kernel, cudaFuncAttributeMaxDynamicSharedMemorySize, (int)asmem);
    attn_kernel<<<dim3(S/64, NH, B), 256, asmem>>>(amask, lw, S);

    // output projection straight into d_out
    gemm_mma<<<dim3(8, M/128), 256, GSMEM>>>(yh, yl, wph, wpl, out, 1024);
}

// round 4
// speedup vs baseline: 3.6699x; 1.8995x over previous
#include <cuda_runtime.h>
#include <cuda_bf16.h>
#include <math.h>
#include <stdint.h>

#define NE   1024
#define NH   16
#define NKV  4
#define HD   64
#define SMAX 2048
#define BMAX 2
#define MMAX (BMAX*SMAX)

typedef unsigned long long ull;

// ---------------- scratch (device globals; no allocation allowed) ----------
__device__ float g_qkv[MMAX * 1536];                  // raw q|k|v per token (fp32)
__device__ __nv_bfloat16 g_xh[(size_t)MMAX*NE];       // x hi/lo split
__device__ __nv_bfloat16 g_xl[(size_t)MMAX*NE];
__device__ __nv_bfloat16 g_wh[1536*1024];             // fused Wq|Wk|Wv hi/lo
__device__ __nv_bfloat16 g_wl[1536*1024];
__device__ __nv_bfloat16 g_wph[1024*1024];            // Wproj hi/lo
__device__ __nv_bfloat16 g_wpl[1024*1024];
__device__ __nv_bfloat16 g_yh[(size_t)MMAX*NE];       // attention out hi/lo
__device__ __nv_bfloat16 g_yl[(size_t)MMAX*NE];
// rope outputs, bf16 hi/lo
__device__ __nv_bfloat16 g_qh[(size_t)BMAX*NH*SMAX*HD];
__device__ __nv_bfloat16 g_ql[(size_t)BMAX*NH*SMAX*HD];
__device__ __nv_bfloat16 g_kh[(size_t)BMAX*NKV*SMAX*HD];
__device__ __nv_bfloat16 g_kl[(size_t)BMAX*NKV*SMAX*HD];
__device__ __nv_bfloat16 g_vh[(size_t)BMAX*NKV*SMAX*HD];
__device__ __nv_bfloat16 g_vl[(size_t)BMAX*NKV*SMAX*HD];

// ---------------- PTX helpers (family-generic only) -------------------------
__device__ __forceinline__ uint32_t smem_to_u32(const void* p) {
    uint32_t a;
    asm("{ .reg .u64 t; cvta.to.shared.u64 t, %1; cvt.u32.u64 %0, t; }" : "=r"(a) : "l"(p));
    return a;
}
__device__ __forceinline__ void ldsm_x4(uint32_t& r0, uint32_t& r1, uint32_t& r2,
                                        uint32_t& r3, uint32_t addr) {
    asm volatile("ldmatrix.sync.aligned.m8n8.x4.shared.b16 {%0,%1,%2,%3}, [%4];"
        : "=r"(r0), "=r"(r1), "=r"(r2), "=r"(r3) : "r"(addr));
}
__device__ __forceinline__ void ldsm_x4_t(uint32_t& r0, uint32_t& r1, uint32_t& r2,
                                          uint32_t& r3, uint32_t addr) {
    asm volatile("ldmatrix.sync.aligned.m8n8.x4.trans.shared.b16 {%0,%1,%2,%3}, [%4];"
        : "=r"(r0), "=r"(r1), "=r"(r2), "=r"(r3) : "r"(addr));
}
__device__ __forceinline__ void mma_bf16(float* c, const uint32_t* a, const uint32_t* b) {
    asm volatile("mma.sync.aligned.m16n8k16.row.col.f32.bf16.bf16.f32 "
        "{%0,%1,%2,%3}, {%4,%5,%6,%7}, {%8,%9}, {%0,%1,%2,%3};"
        : "+f"(c[0]), "+f"(c[1]), "+f"(c[2]), "+f"(c[3])
        : "r"(a[0]), "r"(a[1]), "r"(a[2]), "r"(a[3]), "r"(b[0]), "r"(b[1]));
}
__device__ __forceinline__ void cp16(uint32_t dst, const void* src) {
    asm volatile("cp.async.cg.shared.global [%0], [%1], 16;" :: "r"(dst), "l"(src));
}
#define CP_COMMIT() asm volatile("cp.async.commit_group;" ::: "memory")
#define CP_WAIT(n)  asm volatile("cp.async.wait_group %0;" :: "n"(n) : "memory")

// pack two floats to bf16x2 (hi) and their residuals (lo)
__device__ __forceinline__ void split2(float x, float y, uint32_t& h, uint32_t& l) {
    __nv_bfloat16 hx = __float2bfloat16(x), hy = __float2bfloat16(y);
    __nv_bfloat162 hv(hx, hy);
    h = *(uint32_t*)&hv;
    __nv_bfloat162 lv(__float2bfloat16(x - __bfloat162float(hx)),
                      __float2bfloat16(y - __bfloat162float(hy)));
    l = *(uint32_t*)&lv;
}

// ---------------- fp32 -> bf16 hi/lo split ----------------------------------
__global__ void __launch_bounds__(256) cvt_split(
    const float* __restrict__ in, __nv_bfloat16* __restrict__ h,
    __nv_bfloat16* __restrict__ l, int n4)
{
    int i = blockIdx.x * 256 + threadIdx.x;
    if (i >= n4) return;
    float4 v = ((const float4*)in)[i];
    uint32_t h0, l0, h1, l1;
    split2(v.x, v.y, h0, l0);
    split2(v.z, v.w, h1, l1);
    uint32_t* hp = (uint32_t*)h;
    uint32_t* lp = (uint32_t*)l;
    hp[i*2] = h0; hp[i*2+1] = h1;
    lp[i*2] = l0; lp[i*2+1] = l1;
}

// ---------------- mma.sync bf16-split GEMM ----------------------------------
#define STG_BYTES 65536   /* Ah|Al|Bh|Bl regions, 16KB each */
#define GSMEM (3*STG_BYTES)

__device__ __forceinline__ void gemm_issue_stage(
    uint32_t sbase, int stg, int kc,
    const __nv_bfloat16* __restrict__ Ah, const __nv_bfloat16* __restrict__ Al,
    const __nv_bfloat16* __restrict__ Wh, const __nv_bfloat16* __restrict__ Wl,
    int bm, int bn, int K, int tid)
{
    #pragma unroll
    for (int i = 0; i < 16; i++) {
        const int idx = i * 256 + tid;           // 0..4095
        const int region = idx >> 10;            // 0:Ah 1:Al 2:Bh 3:Bl
        const int cid = idx & 1023;
        const int row = cid >> 3, c16 = cid & 7;
        const uint32_t off = row * 128 + c16 * 16;
        const uint32_t sw = off ^ ((off >> 3) & 0x70);
        const int gk = kc * 64 + c16 * 8;
        const __nv_bfloat16* src;
        if      (region == 0) src = Ah + (size_t)(bm + row) * K + gk;
        else if (region == 1) src = Al + (size_t)(bm + row) * K + gk;
        else if (region == 2) src = Wh + (size_t)(bn + row) * K + gk;
        else                  src = Wl + (size_t)(bn + row) * K + gk;
        cp16(sbase + stg * STG_BYTES + region * 16384 + sw, src);
    }
}

__global__ void __launch_bounds__(256, 1) gemm_mma(
    const __nv_bfloat16* __restrict__ Ah, const __nv_bfloat16* __restrict__ Al,
    const __nv_bfloat16* __restrict__ Wh, const __nv_bfloat16* __restrict__ Wl,
    float* __restrict__ C, int ldc)
{
    constexpr int K = 1024;
    constexpr int NK = K / 64;
    extern __shared__ char gsm[];
    const uint32_t sbase = smem_to_u32(gsm);
    const int tid = threadIdx.x, wid = tid >> 5, lane = tid & 31;
    const int warpM = wid & 3, warpN = wid >> 2;      // 4 x 2 warps
    const int bm = blockIdx.y * 128, bn = blockIdx.x * 128;

    float c[2][8][4];
    #pragma unroll
    for (int mt = 0; mt < 2; mt++)
        #pragma unroll
        for (int n = 0; n < 8; n++)
            #pragma unroll
            for (int j = 0; j < 4; j++) c[mt][n][j] = 0.f;

    const int rIn = lane & 7, mId = lane >> 3;

    gemm_issue_stage(sbase, 0, 0, Ah, Al, Wh, Wl, bm, bn, K, tid); CP_COMMIT();
    gemm_issue_stage(sbase, 1, 1, Ah, Al, Wh, Wl, bm, bn, K, tid); CP_COMMIT();

    for (int kc = 0; kc < NK; kc++) {
        const int stg = kc % 3;
        if (kc + 2 < NK) {
            gemm_issue_stage(sbase, (kc + 2) % 3, kc + 2, Ah, Al, Wh, Wl, bm, bn, K, tid);
            CP_COMMIT();
            CP_WAIT(2);
        } else if (kc + 1 < NK) {
            CP_WAIT(1);
        } else {
            CP_WAIT(0);
        }
        __syncthreads();

        const uint32_t aAh = sbase + stg * STG_BYTES;
        const uint32_t aAl = aAh + 16384;
        const uint32_t aBh = aAl + 16384;
        const uint32_t aBl = aBh + 16384;

        #pragma unroll
        for (int kk = 0; kk < 64; kk += 16) {
            uint32_t ah[2][4], al[2][4];
            #pragma unroll
            for (int mt = 0; mt < 2; mt++) {
                const int row = warpM * 32 + mt * 16 + (mId & 1) * 8 + rIn;
                const int colB = (kk + (mId >> 1) * 8) * 2;
                const uint32_t off = row * 128 + colB;
                const uint32_t sw = off ^ ((off >> 3) & 0x70);
                ldsm_x4(ah[mt][0], ah[mt][1], ah[mt][2], ah[mt][3], aAh + sw);
                ldsm_x4(al[mt][0], al[mt][1], al[mt][2], al[mt][3], aAl + sw);
            }
            uint32_t bh[8][2], bl[8][2];
            #pragma unroll
            for (int nt = 0; nt < 4; nt++) {
                const int row = warpN * 64 + nt * 16 + (mId >> 1) * 8 + rIn;
                const int colB = (kk + (mId & 1) * 8) * 2;
                const uint32_t off = row * 128 + colB;
                const uint32_t sw = off ^ ((off >> 3) & 0x70);
                ldsm_x4(bh[2*nt][0], bh[2*nt][1], bh[2*nt+1][0], bh[2*nt+1][1], aBh + sw);
                ldsm_x4(bl[2*nt][0], bl[2*nt][1], bl[2*nt+1][0], bl[2*nt+1][1], aBl + sw);
            }
            #pragma unroll
            for (int mt = 0; mt < 2; mt++)
                #pragma unroll
                for (int n = 0; n < 8; n++) {
                    mma_bf16(c[mt][n], ah[mt], bh[n]);
                    mma_bf16(c[mt][n], ah[mt], bl[n]);
                    mma_bf16(c[mt][n], al[mt], bh[n]);
                }
        }
        __syncthreads();
    }

    const int g = lane >> 2, t = lane & 3;
    #pragma unroll
    for (int mt = 0; mt < 2; mt++) {
        #pragma unroll
        for (int n = 0; n < 8; n++) {
            const int r0 = bm + warpM * 32 + mt * 16 + g;
            const int col = bn + warpN * 64 + n * 8 + t * 2;
            *(float2*)&C[(size_t)r0 * ldc + col]       = make_float2(c[mt][n][0], c[mt][n][1]);
            *(float2*)&C[(size_t)(r0 + 8) * ldc + col] = make_float2(c[mt][n][2], c[mt][n][3]);
        }
    }
}

// ---------------- rope + rmsnorm + ve-gate -> bf16 hi/lo --------------------
// Q is pre-scaled by 1.2*0.125 (softmax scale folded in); K by 1.2.
__global__ void __launch_bounds__(128) rope_kernel(
    const float* __restrict__ x, const float* __restrict__ ve,
    const float* __restrict__ cosb, const float* __restrict__ sinb,
    const float* __restrict__ Wgate, int S)
{
    const int m = blockIdx.x;
    const int b = m / S, s = m - b * S;
    const int warp = threadIdx.x >> 5, lane = threadIdx.x & 31;
    const float c  = cosb[s*32 + lane];
    const float sn = sinb[s*32 + lane];
    const float* row = g_qkv + (size_t)m * 1536;

    #pragma unroll
    for (int hh = 0; hh < 4; hh++) {
        int h = warp * 4 + hh;
        float t1 = row[h*64 + lane];
        float t2 = row[h*64 + 32 + lane];
        float r1 = t1*c + t2*sn;
        float r2 = t2*c - t1*sn;
        float ss = r1*r1 + r2*r2;
        #pragma unroll
        for (int o = 16; o; o >>= 1) ss += __shfl_xor_sync(0xffffffffu, ss, o);
        float inv = rsqrtf(ss * (1.0f/64.0f) + 1.1920929e-07f) * (1.2f * 0.125f);
        size_t doff = ((size_t)(b*NH + h)*S + s) * HD;
        float qa = r1 * inv, qb = r2 * inv;
        __nv_bfloat16 ha = __float2bfloat16(qa), hb = __float2bfloat16(qb);
        g_qh[doff + lane]      = ha;
        g_qh[doff + 32 + lane] = hb;
        g_ql[doff + lane]      = __float2bfloat16(qa - __bfloat162float(ha));
        g_ql[doff + 32 + lane] = __float2bfloat16(qb - __bfloat162float(hb));
    }
    {
        int h = warp;
        float t1 = row[1024 + h*64 + lane];
        float t2 = row[1024 + h*64 + 32 + lane];
        float r1 = t1*c + t2*sn;
        float r2 = t2*c - t1*sn;
        float ss = r1*r1 + r2*r2;
        #pragma unroll
        for (int o = 16; o; o >>= 1) ss += __shfl_xor_sync(0xffffffffu, ss, o);
        float inv = rsqrtf(ss * (1.0f/64.0f) + 1.1920929e-07f) * 1.2f;
        size_t doff = ((size_t)(b*NKV + h)*S + s) * HD;
        float ka = r1 * inv, kb = r2 * inv;
        __nv_bfloat16 ha = __float2bfloat16(ka), hb = __float2bfloat16(kb);
        g_kh[doff + lane]      = ha;
        g_kh[doff + 32 + lane] = hb;
        g_kl[doff + lane]      = __float2bfloat16(ka - __bfloat162float(ha));
        g_kl[doff + 32 + lane] = __float2bfloat16(kb - __bfloat162float(hb));

        float gz = (lane < 12) ? x[(size_t)m*NE + lane] * Wgate[h*12 + lane] : 0.f;
        #pragma unroll
        for (int o = 16; o; o >>= 1) gz += __shfl_xor_sync(0xffffffffu, gz, o);
        float gate = 3.0f / (1.0f + __expf(-gz));
        float v1 = row[1280 + h*64 + lane]      + gate * ve[(size_t)m*256 + h*64 + lane];
        float v2 = row[1280 + h*64 + 32 + lane] + gate * ve[(size_t)m*256 + h*64 + 32 + lane];
        __nv_bfloat16 hv1 = __float2bfloat16(v1), hv2 = __float2bfloat16(v2);
        g_vh[doff + lane]      = hv1;
        g_vh[doff + 32 + lane] = hv2;
        g_vl[doff + lane]      = __float2bfloat16(v1 - __bfloat162float(hv1));
        g_vl[doff + 32 + lane] = __float2bfloat16(v2 - __bfloat162float(hv2));
    }
}

// ---------------- flash attention on mma.sync tensor cores ------------------
// CTA = 128 thr (4 warps), q-tile 64 (warp = 16 rows), k-tile 64.
// K/V bf16 hi/lo double-buffered via cp.async. S-frag -> P a-frag in-register.
#define AOFF_QH 0
#define AOFF_QL 8192
#define AOFF_STG 16384
#define ASTG_STRIDE 33024   /* Kh,Kl,Vh,Vl (8KB each) + amask (256B) */
#define ASMEM (AOFF_STG + 2*ASTG_STRIDE)

__device__ __forceinline__ void attn_issue_stage(
    uint32_t sbase, int buf,
    const __nv_bfloat16* Kh, const __nv_bfloat16* Kl,
    const __nv_bfloat16* Vh, const __nv_bfloat16* Vl,
    const int* amrow, int tid)
{
    const uint32_t stg = sbase + AOFF_STG + buf * ASTG_STRIDE;
    #pragma unroll
    for (int i = 0; i < 16; i++) {
        const int idx = i * 128 + tid;        // 0..2047
        const int region = idx >> 9;          // 0:Kh 1:Kl 2:Vh 3:Vl
        const int cid = idx & 511;
        const int row = cid >> 3, c16 = cid & 7;
        const uint32_t off = row * 128 + c16 * 16;
        const uint32_t sw = off ^ ((off >> 3) & 0x70);
        const __nv_bfloat16* src;
        if      (region == 0) src = Kh + row * 64 + c16 * 8;
        else if (region == 1) src = Kl + row * 64 + c16 * 8;
        else if (region == 2) src = Vh + row * 64 + c16 * 8;
        else                  src = Vl + row * 64 + c16 * 8;
        cp16(stg + region * 8192 + sw, src);
    }
    if (tid < 16) cp16(stg + 32768 + tid * 16, amrow + tid * 4);
}

__global__ void __launch_bounds__(128) attn_kernel(
    const int* __restrict__ amask, const int* __restrict__ lwp, int S)
{
    extern __shared__ char asm_[];
    const uint32_t sbase = smem_to_u32(asm_);
    const int q0 = blockIdx.x * 64;
    const int h  = blockIdx.y;
    const int bz = blockIdx.z;
    const int kvh = h >> 2;
    const int LW = *lwp;
    const int tid = threadIdx.x, warp = tid >> 5, lane = tid & 31;
    const int rIn = lane & 7, mId = lane >> 3;
    const int g = lane >> 2, t = lane & 3;

    const __nv_bfloat16* Qh0 = g_qh + ((size_t)(bz*NH + h)*S + q0) * HD;
    const __nv_bfloat16* Ql0 = g_ql + ((size_t)(bz*NH + h)*S + q0) * HD;
    const __nv_bfloat16* Kh0 = g_kh + ((size_t)(bz*NKV + kvh)*S) * HD;
    const __nv_bfloat16* Kl0 = g_kl + ((size_t)(bz*NKV + kvh)*S) * HD;
    const __nv_bfloat16* Vh0 = g_vh + ((size_t)(bz*NKV + kvh)*S) * HD;
    const __nv_bfloat16* Vl0 = g_vl + ((size_t)(bz*NKV + kvh)*S) * HD;
    const int* am0 = amask + bz * S;

    // ---- Q -> smem (swizzled) ----
    #pragma unroll
    for (int i = 0; i < 4; i++) {
        const int idx = i * 128 + tid;         // 0..511 chunks of 16B
        const int row = idx >> 3, c16 = idx & 7;
        const uint32_t off = row * 128 + c16 * 16;
        const uint32_t sw = off ^ ((off >> 3) & 0x70);
        *(uint4*)(asm_ + AOFF_QH + sw) = *(const uint4*)(Qh0 + row * 64 + c16 * 8);
        *(uint4*)(asm_ + AOFF_QL + sw) = *(const uint4*)(Ql0 + row * 64 + c16 * 8);
    }

    int kmin = q0 - LW + 1; if (kmin < 0) kmin = 0;
    const int kt0 = kmin >> 6, kt1 = q0 >> 6;
    const int nt = kt1 - kt0 + 1;

    attn_issue_stage(sbase, 0, Kh0 + (size_t)(kt0<<6)*HD, Kl0 + (size_t)(kt0<<6)*HD,
                     Vh0 + (size_t)(kt0<<6)*HD, Vl0 + (size_t)(kt0<<6)*HD,
                     am0 + (kt0<<6), tid);
    CP_COMMIT();
    if (nt > 1) {
        attn_issue_stage(sbase, 1, Kh0 + (size_t)((kt0+1)<<6)*HD, Kl0 + (size_t)((kt0+1)<<6)*HD,
                         Vh0 + (size_t)((kt0+1)<<6)*HD, Vl0 + (size_t)((kt0+1)<<6)*HD,
                         am0 + ((kt0+1)<<6), tid);
        CP_COMMIT();
    }

    __syncthreads();   // Q smem visible

    // ---- Q a-frags (held in regs whole kernel) ----
    uint32_t aqh[4][4], aql[4][4];
    #pragma unroll
    for (int kk = 0; kk < 4; kk++) {
        const int row = warp * 16 + (mId & 1) * 8 + rIn;
        const int colB = (kk * 16 + (mId >> 1) * 8) * 2;
        const uint32_t off = row * 128 + colB;
        const uint32_t sw = off ^ ((off >> 3) & 0x70);
        ldsm_x4(aqh[kk][0], aqh[kk][1], aqh[kk][2], aqh[kk][3], sbase + AOFF_QH + sw);
        ldsm_x4(aql[kk][0], aql[kk][1], aql[kk][2], aql[kk][3], sbase + AOFF_QL + sw);
    }

    // ---- state ----
    float o[8][4];
    #pragma unroll
    for (int j = 0; j < 8; j++)
        #pragma unroll
        for (int e = 0; e < 4; e++) o[j][e] = 0.f;
    float m0 = -1e30f, m1 = -1e30f, l0 = 0.f, l1 = 0.f;
    const int r0g = q0 + warp * 16 + g;     // global q row for e=0,1
    const int r1g = r0g + 8;                // e=2,3

    for (int i = 0; i < nt; i++) {
        const int kt = kt0 + i, buf = i & 1;
        const int k0 = kt << 6;
        if (i + 1 < nt) { CP_WAIT(1); } else { CP_WAIT(0); }
        __syncthreads();

        const uint32_t stg = sbase + AOFF_STG + buf * ASTG_STRIDE;
        const uint32_t sKh = stg, sKl = stg + 8192, sVh = stg + 16384, sVl = stg + 24576;
        const int* sAm = (const int*)(asm_ + AOFF_STG + buf * ASTG_STRIDE + 32768);

        // ---- QK^T (3-split) ----
        float sc[8][4];
        #pragma unroll
        for (int j = 0; j < 8; j++)
            #pragma unroll
            for (int e = 0; e < 4; e++) sc[j][e] = 0.f;

        #pragma unroll
        for (int kk = 0; kk < 4; kk++) {
            uint32_t bh[8][2], bl[8][2];
            #pragma unroll
            for (int ntp = 0; ntp < 4; ntp++) {
                const int row = ntp * 16 + (mId >> 1) * 8 + rIn;
                const int colB = (kk * 16 + (mId & 1) * 8) * 2;
                const uint32_t off = row * 128 + colB;
                const uint32_t sw = off ^ ((off >> 3) & 0x70);
                ldsm_x4(bh[2*ntp][0], bh[2*ntp][1], bh[2*ntp+1][0], bh[2*ntp+1][1], sKh + sw);
                ldsm_x4(bl[2*ntp][0], bl[2*ntp][1], bl[2*ntp+1][0], bl[2*ntp+1][1], sKl + sw);
            }
            #pragma unroll
            for (int j = 0; j < 8; j++) {
                mma_bf16(sc[j], aqh[kk], bh[j]);
                mma_bf16(sc[j], aqh[kk], bl[j]);
                mma_bf16(sc[j], aql[kk], bh[j]);
            }
        }

        // ---- mask + online softmax ----
        float ml0 = -1e30f, ml1 = -1e30f;
        #pragma unroll
        for (int j = 0; j < 8; j++) {
            const int ce = 8*j + 2*t, co = ce + 1;
            const int ae = sAm[ce], ao = sAm[co];
            const int gce = k0 + ce, gco = k0 + co;
            bool ok;
            ok = (gce <= r0g) && (r0g - gce < LW) && ae;
            sc[j][0] = ok ? sc[j][0] : -1e30f;
            ok = (gco <= r0g) && (r0g - gco < LW) && ao;
            sc[j][1] = ok ? sc[j][1] : -1e30f;
            ok = (gce <= r1g) && (r1g - gce < LW) && ae;
            sc[j][2] = ok ? sc[j][2] : -1e30f;
            ok = (gco <= r1g) && (r1g - gco < LW) && ao;
            sc[j][3] = ok ? sc[j][3] : -1e30f;
            ml0 = fmaxf(ml0, fmaxf(sc[j][0], sc[j][1]));
            ml1 = fmaxf(ml1, fmaxf(sc[j][2], sc[j][3]));
        }
        ml0 = fmaxf(ml0, __shfl_xor_sync(0xffffffffu, ml0, 1));
        ml0 = fmaxf(ml0, __shfl_xor_sync(0xffffffffu, ml0, 2));
        ml1 = fmaxf(ml1, __shfl_xor_sync(0xffffffffu, ml1, 1));
        ml1 = fmaxf(ml1, __shfl_xor_sync(0xffffffffu, ml1, 2));
        const float mn0 = fmaxf(m0, ml0), mn1 = fmaxf(m1, ml1);
        const float al0 = __expf(m0 - mn0), al1 = __expf(m1 - mn1);
        m0 = mn0; m1 = mn1;

        float ls0 = 0.f, ls1 = 0.f;
        #pragma unroll
        for (int j = 0; j < 8; j++) {
            float p0 = (sc[j][0] <= -1e29f) ? 0.f : __expf(sc[j][0] - mn0);
            float p1 = (sc[j][1] <= -1e29f) ? 0.f : __expf(sc[j][1] - mn0);
            float p2 = (sc[j][2] <= -1e29f) ? 0.f : __expf(sc[j][2] - mn1);
            float p3 = (sc[j][3] <= -1e29f) ? 0.f : __expf(sc[j][3] - mn1);
            sc[j][0] = p0; sc[j][1] = p1; sc[j][2] = p2; sc[j][3] = p3;
            ls0 += p0 + p1; ls1 += p2 + p3;
        }
        ls0 += __shfl_xor_sync(0xffffffffu, ls0, 1);
        ls0 += __shfl_xor_sync(0xffffffffu, ls0, 2);
        ls1 += __shfl_xor_sync(0xffffffffu, ls1, 1);
        ls1 += __shfl_xor_sync(0xffffffffu, ls1, 2);
        l0 = l0 * al0 + ls0;
        l1 = l1 * al1 + ls1;

        #pragma unroll
        for (int j = 0; j < 8; j++) {
            o[j][0] *= al0; o[j][1] *= al0; o[j][2] *= al1; o[j][3] *= al1;
        }

        // ---- P -> a-frags (hi/lo) in-register ----
        uint32_t pah[4][4], pal[4][4];
        #pragma unroll
        for (int kb = 0; kb < 4; kb++) {
            const int j0 = 2*kb, j1 = 2*kb + 1;
            split2(sc[j0][0], sc[j0][1], pah[kb][0], pal[kb][0]);
            split2(sc[j0][2], sc[j0][3], pah[kb][1], pal[kb][1]);
            split2(sc[j1][0], sc[j1][1], pah[kb][2], pal[kb][2]);
            split2(sc[j1][2], sc[j1][3], pah[kb][3], pal[kb][3]);
        }

        // ---- P V (3-split), V row-major via trans ldmatrix ----
        #pragma unroll
        for (int kb = 0; kb < 4; kb++) {
            uint32_t vh[8][2], vl[8][2];
            #pragma unroll
            for (int dp = 0; dp < 4; dp++) {
                const int row = kb * 16 + (mId & 1) * 8 + rIn;
                const int colB = (dp * 16 + (mId >> 1) * 8) * 2;
                const uint32_t off = row * 128 + colB;
                const uint32_t sw = off ^ ((off >> 3) & 0x70);
                ldsm_x4_t(vh[2*dp][0], vh[2*dp][1], vh[2*dp+1][0], vh[2*dp+1][1], sVh + sw);
                ldsm_x4_t(vl[2*dp][0], vl[2*dp][1], vl[2*dp+1][0], vl[2*dp+1][1], sVl + sw);
            }
            #pragma unroll
            for (int j = 0; j < 8; j++) {
                mma_bf16(o[j], pah[kb], vh[j]);
                mma_bf16(o[j], pah[kb], vl[j]);
                mma_bf16(o[j], pal[kb], vh[j]);
            }
        }

        __syncthreads();   // done reading stage buf
        if (i + 2 < nt) {
            const int kn = (kt + 2) << 6;
            attn_issue_stage(sbase, buf, Kh0 + (size_t)kn*HD, Kl0 + (size_t)kn*HD,
                             Vh0 + (size_t)kn*HD, Vl0 + (size_t)kn*HD, am0 + kn, tid);
            CP_COMMIT();
        }
    }

    // ---- epilogue: write y bf16 hi/lo ----
    const float inv0 = 1.0f / l0, inv1 = 1.0f / l1;
    const size_t tok0 = (size_t)(bz*S + r0g) * NE + h*HD;
    const size_t tok1 = (size_t)(bz*S + r1g) * NE + h*HD;
    #pragma unroll
    for (int j = 0; j < 8; j++) {
        const int d0 = 8*j + 2*t;
        uint32_t hh, ll;
        split2(o[j][0]*inv0, o[j][1]*inv0, hh, ll);
        *(uint32_t*)(g_yh + tok0 + d0) = hh;
        *(uint32_t*)(g_yl + tok0 + d0) = ll;
        split2(o[j][2]*inv1, o[j][3]*inv1, hh, ll);
        *(uint32_t*)(g_yh + tok1 + d0) = hh;
        *(uint32_t*)(g_yl + tok1 + d0) = ll;
    }
}

// ---------------- launch ----------------------------------------------------
extern "C" void kernel_launch(void* const* d_in, const int* in_sizes, int n_in,
                              void* d_out, int out_size)
{
    const float* x     = (const float*)d_in[0];
    const float* ve    = (const float*)d_in[1];
    const float* cosb  = (const float*)d_in[2];
    const float* sinb  = (const float*)d_in[3];
    const float* Wq    = (const float*)d_in[4];
    const float* Wk    = (const float*)d_in[5];
    const float* Wv    = (const float*)d_in[6];
    const float* Wproj = (const float*)d_in[7];
    const float* Wgate = (const float*)d_in[8];
    const int*   amask = (const int*)d_in[9];
    const int*   lw    = (const int*)d_in[10];
    float* out = (float*)d_out;

    const int S = in_sizes[2] / 32;        // cos is (S,1,32)
    const int B = in_sizes[0] / (S * NE);
    const int M = B * S;

    float *qkv_p;
    __nv_bfloat16 *xh, *xl, *wh, *wl, *wph, *wpl, *yh, *yl;
    cudaGetSymbolAddress((void**)&qkv_p, g_qkv);
    cudaGetSymbolAddress((void**)&xh, g_xh);
    cudaGetSymbolAddress((void**)&xl, g_xl);
    cudaGetSymbolAddress((void**)&wh, g_wh);
    cudaGetSymbolAddress((void**)&wl, g_wl);
    cudaGetSymbolAddress((void**)&wph, g_wph);
    cudaGetSymbolAddress((void**)&wpl, g_wpl);
    cudaGetSymbolAddress((void**)&yh, g_yh);
    cudaGetSymbolAddress((void**)&yl, g_yl);

    // fp32 -> bf16 hi/lo splits (x and weights; Wq|Wk|Wv fused row-wise)
    {
        int n4 = M * NE / 4;
        cvt_split<<<(n4 + 255)/256, 256>>>(x, xh, xl, n4);
        n4 = 1024*1024/4;
        cvt_split<<<(n4 + 255)/256, 256>>>(Wq, wh, wl, n4);
        cvt_split<<<(n4 + 255)/256, 256>>>(Wproj, wph, wpl, n4);
        n4 = 256*1024/4;
        cvt_split<<<(n4 + 255)/256, 256>>>(Wk, wh + 1024*1024, wl + 1024*1024, n4);
        cvt_split<<<(n4 + 255)/256, 256>>>(Wv, wh + 1280*1024, wl + 1280*1024, n4);
    }

    cudaFuncSetAttribute(gemm_mma, cudaFuncAttributeMaxDynamicSharedMemorySize, GSMEM);

    // fused QKV projection: [M,1536] = x @ [Wq|Wk|Wv]^T
    gemm_mma<<<dim3(12, M/128), 256, GSMEM>>>(xh, xl, wh, wl, qkv_p, 1536);

    // rope + rmsnorm + gate -> bf16 hi/lo q/k/v
    rope_kernel<<<M, 128>>>(x, ve, cosb, sinb, Wgate, S);

    // attention (tensor-core flash)
    cudaFuncSetAttribute(attn_kernel, cudaFuncAttributeMaxDynamicSharedMemorySize, ASMEM);
    attn_kernel<<<dim3(S/64, NH, B), 128, ASMEM>>>(amask, lw, S);

    // output projection straight into d_out
    gemm_mma<<<dim3(8, M/128), 256, GSMEM>>>(yh, yl, wph, wpl, out, 1024);
}

// round 5
// speedup vs baseline: 3.7154x; 1.0124x over previous
#include <cuda_runtime.h>
#include <cuda_bf16.h>
#include <math.h>
#include <stdint.h>

#define NE   1024
#define NH   16
#define NKV  4
#define HD   64
#define SMAX 2048
#define BMAX 2
#define MMAX (BMAX*SMAX)
#define RMS_EPS 1.1920929e-07f

typedef unsigned long long ull;

// ---------------- scratch (device globals; no allocation allowed) ----------
__device__ __nv_bfloat16 g_xh[(size_t)MMAX*NE];       // x hi/lo split
__device__ __nv_bfloat16 g_xl[(size_t)MMAX*NE];
__device__ __nv_bfloat16 g_wh[1536*1024];             // fused Wq|Wk|Wv hi/lo
__device__ __nv_bfloat16 g_wl[1536*1024];
__device__ __nv_bfloat16 g_wph[1024*1024];            // Wproj hi/lo
__device__ __nv_bfloat16 g_wpl[1024*1024];
__device__ __nv_bfloat16 g_yh[(size_t)MMAX*NE];       // attention out hi/lo
__device__ __nv_bfloat16 g_yl[(size_t)MMAX*NE];
// rope outputs, bf16 hi/lo
__device__ __nv_bfloat16 g_qh[(size_t)BMAX*NH*SMAX*HD];
__device__ __nv_bfloat16 g_ql[(size_t)BMAX*NH*SMAX*HD];
__device__ __nv_bfloat16 g_kh[(size_t)BMAX*NKV*SMAX*HD];
__device__ __nv_bfloat16 g_kl[(size_t)BMAX*NKV*SMAX*HD];
__device__ __nv_bfloat16 g_vh[(size_t)BMAX*NKV*SMAX*HD];
__device__ __nv_bfloat16 g_vl[(size_t)BMAX*NKV*SMAX*HD];

// ---------------- PTX helpers (family-generic only) -------------------------
__device__ __forceinline__ uint32_t smem_to_u32(const void* p) {
    uint32_t a;
    asm("{ .reg .u64 t; cvta.to.shared.u64 t, %1; cvt.u32.u64 %0, t; }" : "=r"(a) : "l"(p));
    return a;
}
__device__ __forceinline__ void ldsm_x4(uint32_t& r0, uint32_t& r1, uint32_t& r2,
                                        uint32_t& r3, uint32_t addr) {
    asm volatile("ldmatrix.sync.aligned.m8n8.x4.shared.b16 {%0,%1,%2,%3}, [%4];"
        : "=r"(r0), "=r"(r1), "=r"(r2), "=r"(r3) : "r"(addr));
}
__device__ __forceinline__ void ldsm_x4_t(uint32_t& r0, uint32_t& r1, uint32_t& r2,
                                          uint32_t& r3, uint32_t addr) {
    asm volatile("ldmatrix.sync.aligned.m8n8.x4.trans.shared.b16 {%0,%1,%2,%3}, [%4];"
        : "=r"(r0), "=r"(r1), "=r"(r2), "=r"(r3) : "r"(addr));
}
__device__ __forceinline__ void mma_bf16(float* c, const uint32_t* a, const uint32_t* b) {
    asm volatile("mma.sync.aligned.m16n8k16.row.col.f32.bf16.bf16.f32 "
        "{%0,%1,%2,%3}, {%4,%5,%6,%7}, {%8,%9}, {%0,%1,%2,%3};"
        : "+f"(c[0]), "+f"(c[1]), "+f"(c[2]), "+f"(c[3])
        : "r"(a[0]), "r"(a[1]), "r"(a[2]), "r"(a[3]), "r"(b[0]), "r"(b[1]));
}
__device__ __forceinline__ void cp16(uint32_t dst, const void* src) {
    asm volatile("cp.async.cg.shared.global [%0], [%1], 16;" :: "r"(dst), "l"(src));
}
#define CP_COMMIT() asm volatile("cp.async.commit_group;" ::: "memory")
#define CP_WAIT(n)  asm volatile("cp.async.wait_group %0;" :: "n"(n) : "memory")

// pack two floats to bf16x2 (hi) and their residuals (lo)
__device__ __forceinline__ void split2(float x, float y, uint32_t& h, uint32_t& l) {
    __nv_bfloat16 hx = __float2bfloat16(x), hy = __float2bfloat16(y);
    __nv_bfloat162 hv(hx, hy);
    h = *(uint32_t*)&hv;
    __nv_bfloat162 lv(__float2bfloat16(x - __bfloat162float(hx)),
                      __float2bfloat16(y - __bfloat162float(hy)));
    l = *(uint32_t*)&lv;
}

// ---------------- merged fp32 -> bf16 hi/lo split ----------------------------
// segments: x (nx4), Wq (256K), Wk (64K), Wv (64K), Wproj (256K)  [in float4s]
__global__ void __launch_bounds__(256) cvt_all(
    const float* __restrict__ x,  const float* __restrict__ Wq,
    const float* __restrict__ Wk, const float* __restrict__ Wv,
    const float* __restrict__ Wproj,
    __nv_bfloat16* __restrict__ xh, __nv_bfloat16* __restrict__ xl, int nx4)
{
    int i = blockIdx.x * 256 + threadIdx.x;
    const float* src;
    __nv_bfloat16 *h, *l;
    int o;
    if (i < nx4) { src = x; h = xh; l = xl; o = i; }
    else {
        i -= nx4;
        if      (i < 262144)  { src = Wq;    h = g_wh;           l = g_wl;           o = i; }
        else if (i < 327680)  { src = Wk;    h = g_wh + 1048576; l = g_wl + 1048576; o = i - 262144; }
        else if (i < 393216)  { src = Wv;    h = g_wh + 1310720; l = g_wl + 1310720; o = i - 327680; }
        else if (i < 655360)  { src = Wproj; h = g_wph;          l = g_wpl;          o = i - 393216; }
        else return;
    }
    float4 v = ((const float4*)src)[o];
    uint32_t h0, l0, h1, l1;
    split2(v.x, v.y, h0, l0);
    split2(v.z, v.w, h1, l1);
    ((uint32_t*)h)[o*2] = h0; ((uint32_t*)h)[o*2+1] = h1;
    ((uint32_t*)l)[o*2] = l0; ((uint32_t*)l)[o*2+1] = l1;
}

// ---------------- shared GEMM mainloop pieces --------------------------------
#define STG_BYTES 65536   /* Ah|Al|Bh|Bl regions, 16KB each */
#define GSMEM (3*STG_BYTES)

__device__ __forceinline__ void gemm_issue_stage(
    uint32_t sbase, int stg, int kc,
    const __nv_bfloat16* __restrict__ Ah, const __nv_bfloat16* __restrict__ Al,
    const __nv_bfloat16* __restrict__ Wh, const __nv_bfloat16* __restrict__ Wl,
    int bm, int bn, int K, int tid)
{
    #pragma unroll
    for (int i = 0; i < 16; i++) {
        const int idx = i * 256 + tid;           // 0..4095
        const int region = idx >> 10;            // 0:Ah 1:Al 2:Bh 3:Bl
        const int cid = idx & 1023;
        const int row = cid >> 3, c16 = cid & 7;
        const uint32_t off = row * 128 + c16 * 16;
        const uint32_t sw = off ^ ((off >> 3) & 0x70);
        const int gk = kc * 64 + c16 * 8;
        const __nv_bfloat16* src;
        if      (region == 0) src = Ah + (size_t)(bm + row) * K + gk;
        else if (region == 1) src = Al + (size_t)(bm + row) * K + gk;
        else if (region == 2) src = Wh + (size_t)(bn + row) * K + gk;
        else                  src = Wl + (size_t)(bn + row) * K + gk;
        cp16(sbase + stg * STG_BYTES + region * 16384 + sw, src);
    }
}

// mainloop computing c[2][8][4] for warp tile 32x64 (warpM, warpN of 4x2)
__device__ __forceinline__ void gemm_mainloop(
    float c[2][8][4], char* gsm, uint32_t sbase,
    const __nv_bfloat16* Ah, const __nv_bfloat16* Al,
    const __nv_bfloat16* Wh, const __nv_bfloat16* Wl,
    int bm, int bn, int tid)
{
    constexpr int K = 1024;
    constexpr int NK = K / 64;
    const int wid = tid >> 5, lane = tid & 31;
    const int warpM = wid & 3, warpN = wid >> 2;
    const int rIn = lane & 7, mId = lane >> 3;

    #pragma unroll
    for (int mt = 0; mt < 2; mt++)
        #pragma unroll
        for (int n = 0; n < 8; n++)
            #pragma unroll
            for (int j = 0; j < 4; j++) c[mt][n][j] = 0.f;

    gemm_issue_stage(sbase, 0, 0, Ah, Al, Wh, Wl, bm, bn, K, tid); CP_COMMIT();
    gemm_issue_stage(sbase, 1, 1, Ah, Al, Wh, Wl, bm, bn, K, tid); CP_COMMIT();

    for (int kc = 0; kc < NK; kc++) {
        const int stg = kc % 3;
        if (kc + 2 < NK) {
            gemm_issue_stage(sbase, (kc + 2) % 3, kc + 2, Ah, Al, Wh, Wl, bm, bn, K, tid);
            CP_COMMIT();
            CP_WAIT(2);
        } else if (kc + 1 < NK) {
            CP_WAIT(1);
        } else {
            CP_WAIT(0);
        }
        __syncthreads();

        const uint32_t aAh = sbase + stg * STG_BYTES;
        const uint32_t aAl = aAh + 16384;
        const uint32_t aBh = aAl + 16384;
        const uint32_t aBl = aBh + 16384;

        #pragma unroll
        for (int kk = 0; kk < 64; kk += 16) {
            uint32_t ah[2][4], al[2][4];
            #pragma unroll
            for (int mt = 0; mt < 2; mt++) {
                const int row = warpM * 32 + mt * 16 + (mId & 1) * 8 + rIn;
                const int colB = (kk + (mId >> 1) * 8) * 2;
                const uint32_t off = row * 128 + colB;
                const uint32_t sw = off ^ ((off >> 3) & 0x70);
                ldsm_x4(ah[mt][0], ah[mt][1], ah[mt][2], ah[mt][3], aAh + sw);
                ldsm_x4(al[mt][0], al[mt][1], al[mt][2], al[mt][3], aAl + sw);
            }
            uint32_t bh[8][2], bl[8][2];
            #pragma unroll
            for (int nt = 0; nt < 4; nt++) {
                const int row = warpN * 64 + nt * 16 + (mId >> 1) * 8 + rIn;
                const int colB = (kk + (mId & 1) * 8) * 2;
                const uint32_t off = row * 128 + colB;
                const uint32_t sw = off ^ ((off >> 3) & 0x70);
                ldsm_x4(bh[2*nt][0], bh[2*nt][1], bh[2*nt+1][0], bh[2*nt+1][1], aBh + sw);
                ldsm_x4(bl[2*nt][0], bl[2*nt][1], bl[2*nt+1][0], bl[2*nt+1][1], aBl + sw);
            }
            #pragma unroll
            for (int mt = 0; mt < 2; mt++)
                #pragma unroll
                for (int n = 0; n < 8; n++) {
                    mma_bf16(c[mt][n], ah[mt], bh[n]);
                    mma_bf16(c[mt][n], ah[mt], bl[n]);
                    mma_bf16(c[mt][n], al[mt], bh[n]);
                }
        }
        __syncthreads();
    }
}

// ---------------- proj GEMM (plain fp32 epilogue) ----------------------------
__global__ void __launch_bounds__(256, 1) gemm_mma(
    const __nv_bfloat16* __restrict__ Ah, const __nv_bfloat16* __restrict__ Al,
    const __nv_bfloat16* __restrict__ Wh, const __nv_bfloat16* __restrict__ Wl,
    float* __restrict__ C, int ldc)
{
    extern __shared__ char gsm[];
    const uint32_t sbase = smem_to_u32(gsm);
    const int tid = threadIdx.x, wid = tid >> 5, lane = tid & 31;
    const int warpM = wid & 3, warpN = wid >> 2;
    const int bm = blockIdx.y * 128, bn = blockIdx.x * 128;

    float c[2][8][4];
    gemm_mainloop(c, gsm, sbase, Ah, Al, Wh, Wl, bm, bn, tid);

    const int g = lane >> 2, t = lane & 3;
    #pragma unroll
    for (int mt = 0; mt < 2; mt++) {
        #pragma unroll
        for (int n = 0; n < 8; n++) {
            const int r0 = bm + warpM * 32 + mt * 16 + g;
            const int col = bn + warpN * 64 + n * 8 + t * 2;
            *(float2*)&C[(size_t)r0 * ldc + col]       = make_float2(c[mt][n][0], c[mt][n][1]);
            *(float2*)&C[(size_t)(r0 + 8) * ldc + col] = make_float2(c[mt][n][2], c[mt][n][3]);
        }
    }
}

// ---------------- QKV GEMM with fused rope/rmsnorm/gate epilogue -------------
// warpN chunk of 64 cols == exactly one head. Each row of a head is owned by
// one quad (t=0..3); rope pair (d, d+32) sits in the same thread (n and n+4).
__global__ void __launch_bounds__(256, 1) gemm_qkv(
    const __nv_bfloat16* __restrict__ Ah, const __nv_bfloat16* __restrict__ Al,
    const __nv_bfloat16* __restrict__ Wh, const __nv_bfloat16* __restrict__ Wl,
    const float* __restrict__ x, const float* __restrict__ ve,
    const float* __restrict__ cosb, const float* __restrict__ sinb,
    const float* __restrict__ Wgate, int S)
{
    extern __shared__ char gsm[];
    const uint32_t sbase = smem_to_u32(gsm);
    const int tid = threadIdx.x, wid = tid >> 5, lane = tid & 31;
    const int warpM = wid & 3, warpN = wid >> 2;
    const int bm = blockIdx.y * 128, bn = blockIdx.x * 128;

    float c[2][8][4];
    gemm_mainloop(c, gsm, sbase, Ah, Al, Wh, Wl, bm, bn, tid);

    const int g = lane >> 2, t = lane & 3;
    const int colbase = bn + warpN * 64;
    const int type = (colbase < 1024) ? 0 : (colbase < 1280 ? 1 : 2);
    const float sQK = (type == 0) ? (1.2f * 0.125f) : 1.2f;

    #pragma unroll
    for (int mt = 0; mt < 2; mt++) {
        #pragma unroll
        for (int e = 0; e < 2; e++) {
            const int row = warpM * 32 + mt * 16 + g + e * 8;
            const int m = bm + row;
            const int b = m / S, s = m - b * S;
            if (type <= 1) {
                float r1[4][2], r2[4][2];
                float ss = 0.f;
                #pragma unroll
                for (int n = 0; n < 4; n++) {
                    const int d0 = n * 8 + 2 * t;
                    const float cs0 = cosb[s*32 + d0], cs1 = cosb[s*32 + d0 + 1];
                    const float sn0 = sinb[s*32 + d0], sn1 = sinb[s*32 + d0 + 1];
                    const float t1a = c[mt][n][2*e],   t1b = c[mt][n][2*e+1];
                    const float t2a = c[mt][n+4][2*e], t2b = c[mt][n+4][2*e+1];
                    r1[n][0] = t1a*cs0 + t2a*sn0;  r1[n][1] = t1b*cs1 + t2b*sn1;
                    r2[n][0] = t2a*cs0 - t1a*sn0;  r2[n][1] = t2b*cs1 - t1b*sn1;
                    ss += r1[n][0]*r1[n][0] + r1[n][1]*r1[n][1]
                        + r2[n][0]*r2[n][0] + r2[n][1]*r2[n][1];
                }
                ss += __shfl_xor_sync(0xffffffffu, ss, 1);
                ss += __shfl_xor_sync(0xffffffffu, ss, 2);
                const float inv = rsqrtf(ss * (1.0f/64.0f) + RMS_EPS) * sQK;
                __nv_bfloat16 *dh, *dl;
                size_t doff;
                if (type == 0) {
                    const int hh = colbase >> 6;
                    doff = ((size_t)(b*NH + hh)*S + s) * HD;
                    dh = g_qh; dl = g_ql;
                } else {
                    const int kh = (colbase - 1024) >> 6;
                    doff = ((size_t)(b*NKV + kh)*S + s) * HD;
                    dh = g_kh; dl = g_kl;
                }
                #pragma unroll
                for (int n = 0; n < 4; n++) {
                    const int d0 = n * 8 + 2 * t;
                    uint32_t hv, lv;
                    split2(r1[n][0]*inv, r1[n][1]*inv, hv, lv);
                    *(uint32_t*)(dh + doff + d0) = hv;
                    *(uint32_t*)(dl + doff + d0) = lv;
                    split2(r2[n][0]*inv, r2[n][1]*inv, hv, lv);
                    *(uint32_t*)(dh + doff + d0 + 32) = hv;
                    *(uint32_t*)(dl + doff + d0 + 32) = lv;
                }
            } else {
                const int kvh = (colbase - 1280) >> 6;
                float gz = 0.f;
                #pragma unroll
                for (int j = 0; j < 3; j++)
                    gz += x[(size_t)m*NE + 3*t + j] * Wgate[kvh*12 + 3*t + j];
                gz += __shfl_xor_sync(0xffffffffu, gz, 1);
                gz += __shfl_xor_sync(0xffffffffu, gz, 2);
                const float gate = 3.0f / (1.0f + __expf(-gz));
                const size_t doff = ((size_t)(b*NKV + kvh)*S + s) * HD;
                const float* vep = ve + (size_t)m*256 + kvh*64;
                #pragma unroll
                for (int n = 0; n < 8; n++) {
                    const int d0 = n * 8 + 2 * t;
                    const float v0 = c[mt][n][2*e]   + gate * vep[d0];
                    const float v1 = c[mt][n][2*e+1] + gate * vep[d0+1];
                    uint32_t hv, lv;
                    split2(v0, v1, hv, lv);
                    *(uint32_t*)(g_vh + doff + d0) = hv;
                    *(uint32_t*)(g_vl + doff + d0) = lv;
                }
            }
        }
    }
}

// ---------------- flash attention on mma.sync tensor cores ------------------
#define AOFF_QH 0
#define AOFF_QL 8192
#define AOFF_STG 16384
#define ASTG_STRIDE 33024   /* Kh,Kl,Vh,Vl (8KB each) + amask (256B) */
#define ASMEM (AOFF_STG + 2*ASTG_STRIDE)

__device__ __forceinline__ void attn_issue_stage(
    uint32_t sbase, int buf,
    const __nv_bfloat16* Kh, const __nv_bfloat16* Kl,
    const __nv_bfloat16* Vh, const __nv_bfloat16* Vl,
    const int* amrow, int tid)
{
    const uint32_t stg = sbase + AOFF_STG + buf * ASTG_STRIDE;
    #pragma unroll
    for (int i = 0; i < 16; i++) {
        const int idx = i * 128 + tid;        // 0..2047
        const int region = idx >> 9;          // 0:Kh 1:Kl 2:Vh 3:Vl
        const int cid = idx & 511;
        const int row = cid >> 3, c16 = cid & 7;
        const uint32_t off = row * 128 + c16 * 16;
        const uint32_t sw = off ^ ((off >> 3) & 0x70);
        const __nv_bfloat16* src;
        if      (region == 0) src = Kh + row * 64 + c16 * 8;
        else if (region == 1) src = Kl + row * 64 + c16 * 8;
        else if (region == 2) src = Vh + row * 64 + c16 * 8;
        else                  src = Vl + row * 64 + c16 * 8;
        cp16(stg + region * 8192 + sw, src);
    }
    if (tid < 16) cp16(stg + 32768 + tid * 16, amrow + tid * 4);
}

__global__ void __launch_bounds__(128) attn_kernel(
    const int* __restrict__ amask, const int* __restrict__ lwp, int S)
{
    extern __shared__ char asm_[];
    const uint32_t sbase = smem_to_u32(asm_);
    const int q0 = blockIdx.x * 64;
    const int h  = blockIdx.y;
    const int bz = blockIdx.z;
    const int kvh = h >> 2;
    const int LW = *lwp;
    const int tid = threadIdx.x, warp = tid >> 5, lane = tid & 31;
    const int rIn = lane & 7, mId = lane >> 3;
    const int g = lane >> 2, t = lane & 3;

    const __nv_bfloat16* Qh0 = g_qh + ((size_t)(bz*NH + h)*S + q0) * HD;
    const __nv_bfloat16* Ql0 = g_ql + ((size_t)(bz*NH + h)*S + q0) * HD;
    const __nv_bfloat16* Kh0 = g_kh + ((size_t)(bz*NKV + kvh)*S) * HD;
    const __nv_bfloat16* Kl0 = g_kl + ((size_t)(bz*NKV + kvh)*S) * HD;
    const __nv_bfloat16* Vh0 = g_vh + ((size_t)(bz*NKV + kvh)*S) * HD;
    const __nv_bfloat16* Vl0 = g_vl + ((size_t)(bz*NKV + kvh)*S) * HD;
    const int* am0 = amask + bz * S;

    #pragma unroll
    for (int i = 0; i < 4; i++) {
        const int idx = i * 128 + tid;
        const int row = idx >> 3, c16 = idx & 7;
        const uint32_t off = row * 128 + c16 * 16;
        const uint32_t sw = off ^ ((off >> 3) & 0x70);
        *(uint4*)(asm_ + AOFF_QH + sw) = *(const uint4*)(Qh0 + row * 64 + c16 * 8);
        *(uint4*)(asm_ + AOFF_QL + sw) = *(const uint4*)(Ql0 + row * 64 + c16 * 8);
    }

    int kmin = q0 - LW + 1; if (kmin < 0) kmin = 0;
    const int kt0 = kmin >> 6, kt1 = q0 >> 6;
    const int nt = kt1 - kt0 + 1;

    attn_issue_stage(sbase, 0, Kh0 + (size_t)(kt0<<6)*HD, Kl0 + (size_t)(kt0<<6)*HD,
                     Vh0 + (size_t)(kt0<<6)*HD, Vl0 + (size_t)(kt0<<6)*HD,
                     am0 + (kt0<<6), tid);
    CP_COMMIT();
    if (nt > 1) {
        attn_issue_stage(sbase, 1, Kh0 + (size_t)((kt0+1)<<6)*HD, Kl0 + (size_t)((kt0+1)<<6)*HD,
                         Vh0 + (size_t)((kt0+1)<<6)*HD, Vl0 + (size_t)((kt0+1)<<6)*HD,
                         am0 + ((kt0+1)<<6), tid);
        CP_COMMIT();
    }

    __syncthreads();

    uint32_t aqh[4][4], aql[4][4];
    #pragma unroll
    for (int kk = 0; kk < 4; kk++) {
        const int row = warp * 16 + (mId & 1) * 8 + rIn;
        const int colB = (kk * 16 + (mId >> 1) * 8) * 2;
        const uint32_t off = row * 128 + colB;
        const uint32_t sw = off ^ ((off >> 3) & 0x70);
        ldsm_x4(aqh[kk][0], aqh[kk][1], aqh[kk][2], aqh[kk][3], sbase + AOFF_QH + sw);
        ldsm_x4(aql[kk][0], aql[kk][1], aql[kk][2], aql[kk][3], sbase + AOFF_QL + sw);
    }

    float o[8][4];
    #pragma unroll
    for (int j = 0; j < 8; j++)
        #pragma unroll
        for (int e = 0; e < 4; e++) o[j][e] = 0.f;
    float m0 = -1e30f, m1 = -1e30f, l0 = 0.f, l1 = 0.f;
    const int r0g = q0 + warp * 16 + g;
    const int r1g = r0g + 8;

    for (int i = 0; i < nt; i++) {
        const int kt = kt0 + i, buf = i & 1;
        const int k0 = kt << 6;
        if (i + 1 < nt) { CP_WAIT(1); } else { CP_WAIT(0); }
        __syncthreads();

        const uint32_t stg = sbase + AOFF_STG + buf * ASTG_STRIDE;
        const uint32_t sKh = stg, sKl = stg + 8192, sVh = stg + 16384, sVl = stg + 24576;
        const int* sAm = (const int*)(asm_ + AOFF_STG + buf * ASTG_STRIDE + 32768);

        float sc[8][4];
        #pragma unroll
        for (int j = 0; j < 8; j++)
            #pragma unroll
            for (int e = 0; e < 4; e++) sc[j][e] = 0.f;

        #pragma unroll
        for (int kk = 0; kk < 4; kk++) {
            uint32_t bh[8][2], bl[8][2];
            #pragma unroll
            for (int ntp = 0; ntp < 4; ntp++) {
                const int row = ntp * 16 + (mId >> 1) * 8 + rIn;
                const int colB = (kk * 16 + (mId & 1) * 8) * 2;
                const uint32_t off = row * 128 + colB;
                const uint32_t sw = off ^ ((off >> 3) & 0x70);
                ldsm_x4(bh[2*ntp][0], bh[2*ntp][1], bh[2*ntp+1][0], bh[2*ntp+1][1], sKh + sw);
                ldsm_x4(bl[2*ntp][0], bl[2*ntp][1], bl[2*ntp+1][0], bl[2*ntp+1][1], sKl + sw);
            }
            #pragma unroll
            for (int j = 0; j < 8; j++) {
                mma_bf16(sc[j], aqh[kk], bh[j]);
                mma_bf16(sc[j], aqh[kk], bl[j]);
                mma_bf16(sc[j], aql[kk], bh[j]);
            }
        }

        float ml0 = -1e30f, ml1 = -1e30f;
        #pragma unroll
        for (int j = 0; j < 8; j++) {
            const int ce = 8*j + 2*t, co = ce + 1;
            const int ae = sAm[ce], ao = sAm[co];
            const int gce = k0 + ce, gco = k0 + co;
            bool ok;
            ok = (gce <= r0g) && (r0g - gce < LW) && ae;
            sc[j][0] = ok ? sc[j][0] : -1e30f;
            ok = (gco <= r0g) && (r0g - gco < LW) && ao;
            sc[j][1] = ok ? sc[j][1] : -1e30f;
            ok = (gce <= r1g) && (r1g - gce < LW) && ae;
            sc[j][2] = ok ? sc[j][2] : -1e30f;
            ok = (gco <= r1g) && (r1g - gco < LW) && ao;
            sc[j][3] = ok ? sc[j][3] : -1e30f;
            ml0 = fmaxf(ml0, fmaxf(sc[j][0], sc[j][1]));
            ml1 = fmaxf(ml1, fmaxf(sc[j][2], sc[j][3]));
        }
        ml0 = fmaxf(ml0, __shfl_xor_sync(0xffffffffu, ml0, 1));
        ml0 = fmaxf(ml0, __shfl_xor_sync(0xffffffffu, ml0, 2));
        ml1 = fmaxf(ml1, __shfl_xor_sync(0xffffffffu, ml1, 1));
        ml1 = fmaxf(ml1, __shfl_xor_sync(0xffffffffu, ml1, 2));
        const float mn0 = fmaxf(m0, ml0), mn1 = fmaxf(m1, ml1);
        const float al0 = __expf(m0 - mn0), al1 = __expf(m1 - mn1);
        m0 = mn0; m1 = mn1;

        float ls0 = 0.f, ls1 = 0.f;
        #pragma unroll
        for (int j = 0; j < 8; j++) {
            float p0 = (sc[j][0] <= -1e29f) ? 0.f : __expf(sc[j][0] - mn0);
            float p1 = (sc[j][1] <= -1e29f) ? 0.f : __expf(sc[j][1] - mn0);
            float p2 = (sc[j][2] <= -1e29f) ? 0.f : __expf(sc[j][2] - mn1);
            float p3 = (sc[j][3] <= -1e29f) ? 0.f : __expf(sc[j][3] - mn1);
            sc[j][0] = p0; sc[j][1] = p1; sc[j][2] = p2; sc[j][3] = p3;
            ls0 += p0 + p1; ls1 += p2 + p3;
        }
        ls0 += __shfl_xor_sync(0xffffffffu, ls0, 1);
        ls0 += __shfl_xor_sync(0xffffffffu, ls0, 2);
        ls1 += __shfl_xor_sync(0xffffffffu, ls1, 1);
        ls1 += __shfl_xor_sync(0xffffffffu, ls1, 2);
        l0 = l0 * al0 + ls0;
        l1 = l1 * al1 + ls1;

        #pragma unroll
        for (int j = 0; j < 8; j++) {
            o[j][0] *= al0; o[j][1] *= al0; o[j][2] *= al1; o[j][3] *= al1;
        }

        uint32_t pah[4][4], pal[4][4];
        #pragma unroll
        for (int kb = 0; kb < 4; kb++) {
            const int j0 = 2*kb, j1 = 2*kb + 1;
            split2(sc[j0][0], sc[j0][1], pah[kb][0], pal[kb][0]);
            split2(sc[j0][2], sc[j0][3], pah[kb][1], pal[kb][1]);
            split2(sc[j1][0], sc[j1][1], pah[kb][2], pal[kb][2]);
            split2(sc[j1][2], sc[j1][3], pah[kb][3], pal[kb][3]);
        }

        #pragma unroll
        for (int kb = 0; kb < 4; kb++) {
            uint32_t vh[8][2], vl[8][2];
            #pragma unroll
            for (int dp = 0; dp < 4; dp++) {
                const int row = kb * 16 + (mId & 1) * 8 + rIn;
                const int colB = (dp * 16 + (mId >> 1) * 8) * 2;
                const uint32_t off = row * 128 + colB;
                const uint32_t sw = off ^ ((off >> 3) & 0x70);
                ldsm_x4_t(vh[2*dp][0], vh[2*dp][1], vh[2*dp+1][0], vh[2*dp+1][1], sVh + sw);
                ldsm_x4_t(vl[2*dp][0], vl[2*dp][1], vl[2*dp+1][0], vl[2*dp+1][1], sVl + sw);
            }
            #pragma unroll
            for (int j = 0; j < 8; j++) {
                mma_bf16(o[j], pah[kb], vh[j]);
                mma_bf16(o[j], pah[kb], vl[j]);
                mma_bf16(o[j], pal[kb], vh[j]);
            }
        }

        __syncthreads();
        if (i + 2 < nt) {
            const int kn = (kt + 2) << 6;
            attn_issue_stage(sbase, buf, Kh0 + (size_t)kn*HD, Kl0 + (size_t)kn*HD,
                             Vh0 + (size_t)kn*HD, Vl0 + (size_t)kn*HD, am0 + kn, tid);
            CP_COMMIT();
        }
    }

    const float inv0 = 1.0f / l0, inv1 = 1.0f / l1;
    const size_t tok0 = (size_t)(bz*S + r0g) * NE + h*HD;
    const size_t tok1 = (size_t)(bz*S + r1g) * NE + h*HD;
    #pragma unroll
    for (int j = 0; j < 8; j++) {
        const int d0 = 8*j + 2*t;
        uint32_t hh, ll;
        split2(o[j][0]*inv0, o[j][1]*inv0, hh, ll);
        *(uint32_t*)(g_yh + tok0 + d0) = hh;
        *(uint32_t*)(g_yl + tok0 + d0) = ll;
        split2(o[j][2]*inv1, o[j][3]*inv1, hh, ll);
        *(uint32_t*)(g_yh + tok1 + d0) = hh;
        *(uint32_t*)(g_yl + tok1 + d0) = ll;
    }
}

// ---------------- launch ----------------------------------------------------
extern "C" void kernel_launch(void* const* d_in, const int* in_sizes, int n_in,
                              void* d_out, int out_size)
{
    const float* x     = (const float*)d_in[0];
    const float* ve    = (const float*)d_in[1];
    const float* cosb  = (const float*)d_in[2];
    const float* sinb  = (const float*)d_in[3];
    const float* Wq    = (const float*)d_in[4];
    const float* Wk    = (const float*)d_in[5];
    const float* Wv    = (const float*)d_in[6];
    const float* Wproj = (const float*)d_in[7];
    const float* Wgate = (const float*)d_in[8];
    const int*   amask = (const int*)d_in[9];
    const int*   lw    = (const int*)d_in[10];
    float* out = (float*)d_out;

    const int S = in_sizes[2] / 32;        // cos is (S,1,32)
    const int B = in_sizes[0] / (S * NE);
    const int M = B * S;

    __nv_bfloat16 *xh, *xl, *wh, *wl, *wph, *wpl, *yh, *yl;
    cudaGetSymbolAddress((void**)&xh, g_xh);
    cudaGetSymbolAddress((void**)&xl, g_xl);
    cudaGetSymbolAddress((void**)&wh, g_wh);
    cudaGetSymbolAddress((void**)&wl, g_wl);
    cudaGetSymbolAddress((void**)&wph, g_wph);
    cudaGetSymbolAddress((void**)&wpl, g_wpl);
    cudaGetSymbolAddress((void**)&yh, g_yh);
    cudaGetSymbolAddress((void**)&yl, g_yl);

    // merged fp32 -> bf16 hi/lo splits
    const int nx4 = M * NE / 4;
    const int ntot = nx4 + 655360;
    cvt_all<<<(ntot + 255)/256, 256>>>(x, Wq, Wk, Wv, Wproj, xh, xl, nx4);

    cudaFuncSetAttribute(gemm_qkv, cudaFuncAttributeMaxDynamicSharedMemorySize, GSMEM);
    cudaFuncSetAttribute(gemm_mma, cudaFuncAttributeMaxDynamicSharedMemorySize, GSMEM);

    // fused QKV projection + rope/rmsnorm/gate epilogue
    gemm_qkv<<<dim3(12, M/128), 256, GSMEM>>>(xh, xl, wh, wl,
                                              x, ve, cosb, sinb, Wgate, S);

    // attention (tensor-core flash)
    cudaFuncSetAttribute(attn_kernel, cudaFuncAttributeMaxDynamicSharedMemorySize, ASMEM);
    attn_kernel<<<dim3(S/64, NH, B), 128, ASMEM>>>(amask, lw, S);

    // output projection straight into d_out
    gemm_mma<<<dim3(8, M/128), 256, GSMEM>>>(yh, yl, wph, wpl, out, 1024);
}

// round 6
// speedup vs baseline: 7.8918x; 2.1241x over previous
#include <cuda_runtime.h>
#include <cuda_fp16.h>
#include <math.h>
#include <stdint.h>

#define NE   1024
#define NH   16
#define NKV  4
#define HD   64
#define SMAX 2048
#define BMAX 2
#define MMAX (BMAX*SMAX)
#define RMS_EPS 1.1920929e-07f

// ---------------- scratch (device globals; no allocation allowed) ----------
__device__ __half g_x[(size_t)MMAX*NE];          // x fp16
__device__ __half g_w[1536*1024];                // fused Wq|Wk|Wv fp16
__device__ __half g_wp[1024*1024];               // Wproj fp16
__device__ __half g_y[(size_t)MMAX*NE];          // attention out fp16
__device__ __half g_q[(size_t)BMAX*NH*SMAX*HD];  // roped q (scale folded)
__device__ __half g_k[(size_t)BMAX*NKV*SMAX*HD];
__device__ __half g_v[(size_t)BMAX*NKV*SMAX*HD];

// ---------------- PTX helpers (family-generic only) -------------------------
__device__ __forceinline__ uint32_t smem_to_u32(const void* p) {
    uint32_t a;
    asm("{ .reg .u64 t; cvta.to.shared.u64 t, %1; cvt.u32.u64 %0, t; }" : "=r"(a) : "l"(p));
    return a;
}
__device__ __forceinline__ void ldsm_x4(uint32_t& r0, uint32_t& r1, uint32_t& r2,
                                        uint32_t& r3, uint32_t addr) {
    asm volatile("ldmatrix.sync.aligned.m8n8.x4.shared.b16 {%0,%1,%2,%3}, [%4];"
        : "=r"(r0), "=r"(r1), "=r"(r2), "=r"(r3) : "r"(addr));
}
__device__ __forceinline__ void ldsm_x4_t(uint32_t& r0, uint32_t& r1, uint32_t& r2,
                                          uint32_t& r3, uint32_t addr) {
    asm volatile("ldmatrix.sync.aligned.m8n8.x4.trans.shared.b16 {%0,%1,%2,%3}, [%4];"
        : "=r"(r0), "=r"(r1), "=r"(r2), "=r"(r3) : "r"(addr));
}
__device__ __forceinline__ void mma_f16(float* c, const uint32_t* a, const uint32_t* b) {
    asm volatile("mma.sync.aligned.m16n8k16.row.col.f32.f16.f16.f32 "
        "{%0,%1,%2,%3}, {%4,%5,%6,%7}, {%8,%9}, {%0,%1,%2,%3};"
        : "+f"(c[0]), "+f"(c[1]), "+f"(c[2]), "+f"(c[3])
        : "r"(a[0]), "r"(a[1]), "r"(a[2]), "r"(a[3]), "r"(b[0]), "r"(b[1]));
}
__device__ __forceinline__ void cp16(uint32_t dst, const void* src) {
    asm volatile("cp.async.cg.shared.global [%0], [%1], 16;" :: "r"(dst), "l"(src));
}
#define CP_COMMIT() asm volatile("cp.async.commit_group;" ::: "memory")
#define CP_WAIT(n)  asm volatile("cp.async.wait_group %0;" :: "n"(n) : "memory")

__device__ __forceinline__ uint32_t pack_h2(float x, float y) {
    __half2 h = __floats2half2_rn(x, y);
    return *(uint32_t*)&h;
}

// ---------------- merged fp32 -> fp16 convert --------------------------------
// segments (float4 units): x (nx4), Wq (256K), Wk (64K), Wv (64K), Wproj (256K)
__global__ void __launch_bounds__(256) cvt_all(
    const float* __restrict__ x,  const float* __restrict__ Wq,
    const float* __restrict__ Wk, const float* __restrict__ Wv,
    const float* __restrict__ Wproj, __half* __restrict__ xo, int nx4)
{
    int i = blockIdx.x * 256 + threadIdx.x;
    const float* src;
    __half* h;
    int o;
    if (i < nx4) { src = x; h = xo; o = i; }
    else {
        i -= nx4;
        if      (i < 262144)  { src = Wq;    h = g_w;           o = i; }
        else if (i < 327680)  { src = Wk;    h = g_w + 1048576; o = i - 262144; }
        else if (i < 393216)  { src = Wv;    h = g_w + 1310720; o = i - 327680; }
        else if (i < 655360)  { src = Wproj; h = g_wp;          o = i - 393216; }
        else return;
    }
    float4 v = ((const float4*)src)[o];
    ((uint32_t*)h)[o*2]   = pack_h2(v.x, v.y);
    ((uint32_t*)h)[o*2+1] = pack_h2(v.z, v.w);
}

// ---------------- fp16 mma.sync GEMM mainloop --------------------------------
#define STG_BYTES 32768   /* A|B regions, 16KB each */
#define GSMEM (3*STG_BYTES)

__device__ __forceinline__ void gemm_issue_stage(
    uint32_t sbase, int stg, int kc,
    const __half* __restrict__ A, const __half* __restrict__ W,
    int bm, int bn, int K, int tid)
{
    #pragma unroll
    for (int i = 0; i < 8; i++) {
        const int idx = i * 256 + tid;           // 0..2047
        const int region = idx >> 10;            // 0:A 1:W
        const int cid = idx & 1023;
        const int row = cid >> 3, c16 = cid & 7;
        const uint32_t off = row * 128 + c16 * 16;
        const uint32_t sw = off ^ ((off >> 3) & 0x70);
        const int gk = kc * 64 + c16 * 8;
        const __half* src = region ? (W + (size_t)(bn + row) * K + gk)
                                   : (A + (size_t)(bm + row) * K + gk);
        cp16(sbase + stg * STG_BYTES + region * 16384 + sw, src);
    }
}

__device__ __forceinline__ void gemm_mainloop(
    float c[2][8][4], uint32_t sbase,
    const __half* A, const __half* W, int bm, int bn, int tid)
{
    constexpr int K = 1024;
    constexpr int NK = K / 64;
    const int wid = tid >> 5, lane = tid & 31;
    const int warpM = wid & 3, warpN = wid >> 2;
    const int rIn = lane & 7, mId = lane >> 3;

    #pragma unroll
    for (int mt = 0; mt < 2; mt++)
        #pragma unroll
        for (int n = 0; n < 8; n++)
            #pragma unroll
            for (int j = 0; j < 4; j++) c[mt][n][j] = 0.f;

    gemm_issue_stage(sbase, 0, 0, A, W, bm, bn, K, tid); CP_COMMIT();
    gemm_issue_stage(sbase, 1, 1, A, W, bm, bn, K, tid); CP_COMMIT();

    for (int kc = 0; kc < NK; kc++) {
        const int stg = kc % 3;
        if (kc + 2 < NK) {
            gemm_issue_stage(sbase, (kc + 2) % 3, kc + 2, A, W, bm, bn, K, tid);
            CP_COMMIT();
            CP_WAIT(2);
        } else if (kc + 1 < NK) {
            CP_WAIT(1);
        } else {
            CP_WAIT(0);
        }
        __syncthreads();

        const uint32_t aA = sbase + stg * STG_BYTES;
        const uint32_t aB = aA + 16384;

        #pragma unroll
        for (int kk = 0; kk < 64; kk += 16) {
            uint32_t a[2][4];
            #pragma unroll
            for (int mt = 0; mt < 2; mt++) {
                const int row = warpM * 32 + mt * 16 + (mId & 1) * 8 + rIn;
                const int colB = (kk + (mId >> 1) * 8) * 2;
                const uint32_t off = row * 128 + colB;
                const uint32_t sw = off ^ ((off >> 3) & 0x70);
                ldsm_x4(a[mt][0], a[mt][1], a[mt][2], a[mt][3], aA + sw);
            }
            uint32_t b[8][2];
            #pragma unroll
            for (int nt = 0; nt < 4; nt++) {
                const int row = warpN * 64 + nt * 16 + (mId >> 1) * 8 + rIn;
                const int colB = (kk + (mId & 1) * 8) * 2;
                const uint32_t off = row * 128 + colB;
                const uint32_t sw = off ^ ((off >> 3) & 0x70);
                ldsm_x4(b[2*nt][0], b[2*nt][1], b[2*nt+1][0], b[2*nt+1][1], aB + sw);
            }
            #pragma unroll
            for (int mt = 0; mt < 2; mt++)
                #pragma unroll
                for (int n = 0; n < 8; n++)
                    mma_f16(c[mt][n], a[mt], b[n]);
        }
        __syncthreads();
    }
}

// ---------------- proj GEMM (fp32 out) ---------------------------------------
__global__ void __launch_bounds__(256, 2) gemm_mma(
    const __half* __restrict__ A, const __half* __restrict__ W,
    float* __restrict__ C, int ldc)
{
    extern __shared__ char gsm[];
    const uint32_t sbase = smem_to_u32(gsm);
    const int tid = threadIdx.x, wid = tid >> 5, lane = tid & 31;
    const int warpM = wid & 3, warpN = wid >> 2;
    const int bm = blockIdx.y * 128, bn = blockIdx.x * 128;

    float c[2][8][4];
    gemm_mainloop(c, sbase, A, W, bm, bn, tid);

    const int g = lane >> 2, t = lane & 3;
    #pragma unroll
    for (int mt = 0; mt < 2; mt++) {
        #pragma unroll
        for (int n = 0; n < 8; n++) {
            const int r0 = bm + warpM * 32 + mt * 16 + g;
            const int col = bn + warpN * 64 + n * 8 + t * 2;
            *(float2*)&C[(size_t)r0 * ldc + col]       = make_float2(c[mt][n][0], c[mt][n][1]);
            *(float2*)&C[(size_t)(r0 + 8) * ldc + col] = make_float2(c[mt][n][2], c[mt][n][3]);
        }
    }
}

// ---------------- QKV GEMM with fused rope/rmsnorm/gate epilogue -------------
__global__ void __launch_bounds__(256, 2) gemm_qkv(
    const __half* __restrict__ A, const __half* __restrict__ W,
    const float* __restrict__ x, const float* __restrict__ ve,
    const float* __restrict__ cosb, const float* __restrict__ sinb,
    const float* __restrict__ Wgate, int S)
{
    extern __shared__ char gsm[];
    const uint32_t sbase = smem_to_u32(gsm);
    const int tid = threadIdx.x, wid = tid >> 5, lane = tid & 31;
    const int warpM = wid & 3, warpN = wid >> 2;
    const int bm = blockIdx.y * 128, bn = blockIdx.x * 128;

    float c[2][8][4];
    gemm_mainloop(c, sbase, A, W, bm, bn, tid);

    const int g = lane >> 2, t = lane & 3;
    const int colbase = bn + warpN * 64;
    const int type = (colbase < 1024) ? 0 : (colbase < 1280 ? 1 : 2);
    const float sQK = (type == 0) ? (1.2f * 0.125f) : 1.2f;

    #pragma unroll
    for (int mt = 0; mt < 2; mt++) {
        #pragma unroll
        for (int e = 0; e < 2; e++) {
            const int row = warpM * 32 + mt * 16 + g + e * 8;
            const int m = bm + row;
            const int b = m / S, s = m - b * S;
            if (type <= 1) {
                float r1[4][2], r2[4][2];
                float ss = 0.f;
                #pragma unroll
                for (int n = 0; n < 4; n++) {
                    const int d0 = n * 8 + 2 * t;
                    const float cs0 = cosb[s*32 + d0], cs1 = cosb[s*32 + d0 + 1];
                    const float sn0 = sinb[s*32 + d0], sn1 = sinb[s*32 + d0 + 1];
                    const float t1a = c[mt][n][2*e],   t1b = c[mt][n][2*e+1];
                    const float t2a = c[mt][n+4][2*e], t2b = c[mt][n+4][2*e+1];
                    r1[n][0] = t1a*cs0 + t2a*sn0;  r1[n][1] = t1b*cs1 + t2b*sn1;
                    r2[n][0] = t2a*cs0 - t1a*sn0;  r2[n][1] = t2b*cs1 - t1b*sn1;
                    ss += r1[n][0]*r1[n][0] + r1[n][1]*r1[n][1]
                        + r2[n][0]*r2[n][0] + r2[n][1]*r2[n][1];
                }
                ss += __shfl_xor_sync(0xffffffffu, ss, 1);
                ss += __shfl_xor_sync(0xffffffffu, ss, 2);
                const float inv = rsqrtf(ss * (1.0f/64.0f) + RMS_EPS) * sQK;
                __half* dst;
                size_t doff;
                if (type == 0) {
                    const int hh = colbase >> 6;
                    doff = ((size_t)(b*NH + hh)*S + s) * HD;
                    dst = g_q;
                } else {
                    const int kh = (colbase - 1024) >> 6;
                    doff = ((size_t)(b*NKV + kh)*S + s) * HD;
                    dst = g_k;
                }
                #pragma unroll
                for (int n = 0; n < 4; n++) {
                    const int d0 = n * 8 + 2 * t;
                    *(uint32_t*)(dst + doff + d0)      = pack_h2(r1[n][0]*inv, r1[n][1]*inv);
                    *(uint32_t*)(dst + doff + d0 + 32) = pack_h2(r2[n][0]*inv, r2[n][1]*inv);
                }
            } else {
                const int kvh = (colbase - 1280) >> 6;
                float gz = 0.f;
                #pragma unroll
                for (int j = 0; j < 3; j++)
                    gz += x[(size_t)m*NE + 3*t + j] * Wgate[kvh*12 + 3*t + j];
                gz += __shfl_xor_sync(0xffffffffu, gz, 1);
                gz += __shfl_xor_sync(0xffffffffu, gz, 2);
                const float gate = 3.0f / (1.0f + __expf(-gz));
                const size_t doff = ((size_t)(b*NKV + kvh)*S + s) * HD;
                const float* vep = ve + (size_t)m*256 + kvh*64;
                #pragma unroll
                for (int n = 0; n < 8; n++) {
                    const int d0 = n * 8 + 2 * t;
                    const float v0 = c[mt][n][2*e]   + gate * vep[d0];
                    const float v1 = c[mt][n][2*e+1] + gate * vep[d0+1];
                    *(uint32_t*)(g_v + doff + d0) = pack_h2(v0, v1);
                }
            }
        }
    }
}

// ---------------- flash attention on fp16 mma.sync ---------------------------
#define AOFF_Q   0
#define AOFF_STG 8192
#define ASTG_STRIDE 16640   /* K (8KB) + V (8KB) + amask (256B) */
#define ASMEM (AOFF_STG + 2*ASTG_STRIDE)

__device__ __forceinline__ void attn_issue_stage(
    uint32_t sbase, int buf,
    const __half* K, const __half* V, const int* amrow, int tid)
{
    const uint32_t stg = sbase + AOFF_STG + buf * ASTG_STRIDE;
    #pragma unroll
    for (int i = 0; i < 8; i++) {
        const int idx = i * 128 + tid;        // 0..1023
        const int region = idx >> 9;          // 0:K 1:V
        const int cid = idx & 511;
        const int row = cid >> 3, c16 = cid & 7;
        const uint32_t off = row * 128 + c16 * 16;
        const uint32_t sw = off ^ ((off >> 3) & 0x70);
        const __half* src = region ? (V + row * 64 + c16 * 8) : (K + row * 64 + c16 * 8);
        cp16(stg + region * 8192 + sw, src);
    }
    if (tid < 16) cp16(stg + 16384 + tid * 16, amrow + tid * 4);
}

__global__ void __launch_bounds__(128) attn_kernel(
    const int* __restrict__ amask, const int* __restrict__ lwp, int S)
{
    extern __shared__ char asm_[];
    const uint32_t sbase = smem_to_u32(asm_);
    const int q0 = blockIdx.x * 64;
    const int h  = blockIdx.y;
    const int bz = blockIdx.z;
    const int kvh = h >> 2;
    const int LW = *lwp;
    const int tid = threadIdx.x, warp = tid >> 5, lane = tid & 31;
    const int rIn = lane & 7, mId = lane >> 3;
    const int g = lane >> 2, t = lane & 3;

    const __half* Q0 = g_q + ((size_t)(bz*NH + h)*S + q0) * HD;
    const __half* K0 = g_k + ((size_t)(bz*NKV + kvh)*S) * HD;
    const __half* V0 = g_v + ((size_t)(bz*NKV + kvh)*S) * HD;
    const int* am0 = amask + bz * S;

    #pragma unroll
    for (int i = 0; i < 4; i++) {
        const int idx = i * 128 + tid;
        const int row = idx >> 3, c16 = idx & 7;
        const uint32_t off = row * 128 + c16 * 16;
        const uint32_t sw = off ^ ((off >> 3) & 0x70);
        *(uint4*)(asm_ + AOFF_Q + sw) = *(const uint4*)(Q0 + row * 64 + c16 * 8);
    }

    int kmin = q0 - LW + 1; if (kmin < 0) kmin = 0;
    const int kt0 = kmin >> 6, kt1 = q0 >> 6;
    const int nt = kt1 - kt0 + 1;

    attn_issue_stage(sbase, 0, K0 + (size_t)(kt0<<6)*HD, V0 + (size_t)(kt0<<6)*HD,
                     am0 + (kt0<<6), tid);
    CP_COMMIT();
    if (nt > 1) {
        attn_issue_stage(sbase, 1, K0 + (size_t)((kt0+1)<<6)*HD, V0 + (size_t)((kt0+1)<<6)*HD,
                         am0 + ((kt0+1)<<6), tid);
        CP_COMMIT();
    }

    __syncthreads();

    uint32_t aq[4][4];
    #pragma unroll
    for (int kk = 0; kk < 4; kk++) {
        const int row = warp * 16 + (mId & 1) * 8 + rIn;
        const int colB = (kk * 16 + (mId >> 1) * 8) * 2;
        const uint32_t off = row * 128 + colB;
        const uint32_t sw = off ^ ((off >> 3) & 0x70);
        ldsm_x4(aq[kk][0], aq[kk][1], aq[kk][2], aq[kk][3], sbase + AOFF_Q + sw);
    }

    float o[8][4];
    #pragma unroll
    for (int j = 0; j < 8; j++)
        #pragma unroll
        for (int e = 0; e < 4; e++) o[j][e] = 0.f;
    float m0 = -1e30f, m1 = -1e30f, l0 = 0.f, l1 = 0.f;
    const int r0g = q0 + warp * 16 + g;
    const int r1g = r0g + 8;

    for (int i = 0; i < nt; i++) {
        const int kt = kt0 + i, buf = i & 1;
        const int k0 = kt << 6;
        if (i + 1 < nt) { CP_WAIT(1); } else { CP_WAIT(0); }
        __syncthreads();

        const uint32_t stg = sbase + AOFF_STG + buf * ASTG_STRIDE;
        const uint32_t sK = stg, sV = stg + 8192;
        const int* sAm = (const int*)(asm_ + AOFF_STG + buf * ASTG_STRIDE + 16384);

        float sc[8][4];
        #pragma unroll
        for (int j = 0; j < 8; j++)
            #pragma unroll
            for (int e = 0; e < 4; e++) sc[j][e] = 0.f;

        #pragma unroll
        for (int kk = 0; kk < 4; kk++) {
            uint32_t b[8][2];
            #pragma unroll
            for (int ntp = 0; ntp < 4; ntp++) {
                const int row = ntp * 16 + (mId >> 1) * 8 + rIn;
                const int colB = (kk * 16 + (mId & 1) * 8) * 2;
                const uint32_t off = row * 128 + colB;
                const uint32_t sw = off ^ ((off >> 3) & 0x70);
                ldsm_x4(b[2*ntp][0], b[2*ntp][1], b[2*ntp+1][0], b[2*ntp+1][1], sK + sw);
            }
            #pragma unroll
            for (int j = 0; j < 8; j++)
                mma_f16(sc[j], aq[kk], b[j]);
        }

        float ml0 = -1e30f, ml1 = -1e30f;
        #pragma unroll
        for (int j = 0; j < 8; j++) {
            const int ce = 8*j + 2*t, co = ce + 1;
            const int ae = sAm[ce], ao = sAm[co];
            const int gce = k0 + ce, gco = k0 + co;
            bool ok;
            ok = (gce <= r0g) && (r0g - gce < LW) && ae;
            sc[j][0] = ok ? sc[j][0] : -1e30f;
            ok = (gco <= r0g) && (r0g - gco < LW) && ao;
            sc[j][1] = ok ? sc[j][1] : -1e30f;
            ok = (gce <= r1g) && (r1g - gce < LW) && ae;
            sc[j][2] = ok ? sc[j][2] : -1e30f;
            ok = (gco <= r1g) && (r1g - gco < LW) && ao;
            sc[j][3] = ok ? sc[j][3] : -1e30f;
            ml0 = fmaxf(ml0, fmaxf(sc[j][0], sc[j][1]));
            ml1 = fmaxf(ml1, fmaxf(sc[j][2], sc[j][3]));
        }
        ml0 = fmaxf(ml0, __shfl_xor_sync(0xffffffffu, ml0, 1));
        ml0 = fmaxf(ml0, __shfl_xor_sync(0xffffffffu, ml0, 2));
        ml1 = fmaxf(ml1, __shfl_xor_sync(0xffffffffu, ml1, 1));
        ml1 = fmaxf(ml1, __shfl_xor_sync(0xffffffffu, ml1, 2));
        const float mn0 = fmaxf(m0, ml0), mn1 = fmaxf(m1, ml1);
        const float al0 = __expf(m0 - mn0), al1 = __expf(m1 - mn1);
        m0 = mn0; m1 = mn1;

        float ls0 = 0.f, ls1 = 0.f;
        #pragma unroll
        for (int j = 0; j < 8; j++) {
            float p0 = (sc[j][0] <= -1e29f) ? 0.f : __expf(sc[j][0] - mn0);
            float p1 = (sc[j][1] <= -1e29f) ? 0.f : __expf(sc[j][1] - mn0);
            float p2 = (sc[j][2] <= -1e29f) ? 0.f : __expf(sc[j][2] - mn1);
            float p3 = (sc[j][3] <= -1e29f) ? 0.f : __expf(sc[j][3] - mn1);
            sc[j][0] = p0; sc[j][1] = p1; sc[j][2] = p2; sc[j][3] = p3;
            ls0 += p0 + p1; ls1 += p2 + p3;
        }
        ls0 += __shfl_xor_sync(0xffffffffu, ls0, 1);
        ls0 += __shfl_xor_sync(0xffffffffu, ls0, 2);
        ls1 += __shfl_xor_sync(0xffffffffu, ls1, 1);
        ls1 += __shfl_xor_sync(0xffffffffu, ls1, 2);
        l0 = l0 * al0 + ls0;
        l1 = l1 * al1 + ls1;

        #pragma unroll
        for (int j = 0; j < 8; j++) {
            o[j][0] *= al0; o[j][1] *= al0; o[j][2] *= al1; o[j][3] *= al1;
        }

        uint32_t pa[4][4];
        #pragma unroll
        for (int kb = 0; kb < 4; kb++) {
            const int j0 = 2*kb, j1 = 2*kb + 1;
            pa[kb][0] = pack_h2(sc[j0][0], sc[j0][1]);
            pa[kb][1] = pack_h2(sc[j0][2], sc[j0][3]);
            pa[kb][2] = pack_h2(sc[j1][0], sc[j1][1]);
            pa[kb][3] = pack_h2(sc[j1][2], sc[j1][3]);
        }

        #pragma unroll
        for (int kb = 0; kb < 4; kb++) {
            uint32_t v[8][2];
            #pragma unroll
            for (int dp = 0; dp < 4; dp++) {
                const int row = kb * 16 + (mId & 1) * 8 + rIn;
                const int colB = (dp * 16 + (mId >> 1) * 8) * 2;
                const uint32_t off = row * 128 + colB;
                const uint32_t sw = off ^ ((off >> 3) & 0x70);
                ldsm_x4_t(v[2*dp][0], v[2*dp][1], v[2*dp+1][0], v[2*dp+1][1], sV + sw);
            }
            #pragma unroll
            for (int j = 0; j < 8; j++)
                mma_f16(o[j], pa[kb], v[j]);
        }

        __syncthreads();
        if (i + 2 < nt) {
            const int kn = (kt + 2) << 6;
            attn_issue_stage(sbase, buf, K0 + (size_t)kn*HD, V0 + (size_t)kn*HD,
                             am0 + kn, tid);
            CP_COMMIT();
        }
    }

    const float inv0 = 1.0f / l0, inv1 = 1.0f / l1;
    const size_t tok0 = (size_t)(bz*S + r0g) * NE + h*HD;
    const size_t tok1 = (size_t)(bz*S + r1g) * NE + h*HD;
    #pragma unroll
    for (int j = 0; j < 8; j++) {
        const int d0 = 8*j + 2*t;
        *(uint32_t*)(g_y + tok0 + d0) = pack_h2(o[j][0]*inv0, o[j][1]*inv0);
        *(uint32_t*)(g_y + tok1 + d0) = pack_h2(o[j][2]*inv1, o[j][3]*inv1);
    }
}

// ---------------- launch ----------------------------------------------------
extern "C" void kernel_launch(void* const* d_in, const int* in_sizes, int n_in,
                              void* d_out, int out_size)
{
    const float* x     = (const float*)d_in[0];
    const float* ve    = (const float*)d_in[1];
    const float* cosb  = (const float*)d_in[2];
    const float* sinb  = (const float*)d_in[3];
    const float* Wq    = (const float*)d_in[4];
    const float* Wk    = (const float*)d_in[5];
    const float* Wv    = (const float*)d_in[6];
    const float* Wproj = (const float*)d_in[7];
    const float* Wgate = (const float*)d_in[8];
    const int*   amask = (const int*)d_in[9];
    const int*   lw    = (const int*)d_in[10];
    float* out = (float*)d_out;

    const int S = in_sizes[2] / 32;        // cos is (S,1,32)
    const int B = in_sizes[0] / (S * NE);
    const int M = B * S;

    __half *xp, *wp, *wpp, *yp;
    cudaGetSymbolAddress((void**)&xp,  g_x);
    cudaGetSymbolAddress((void**)&wp,  g_w);
    cudaGetSymbolAddress((void**)&wpp, g_wp);
    cudaGetSymbolAddress((void**)&yp,  g_y);

    // merged fp32 -> fp16 converts
    const int nx4 = M * NE / 4;
    const int ntot = nx4 + 655360;
    cvt_all<<<(ntot + 255)/256, 256>>>(x, Wq, Wk, Wv, Wproj, xp, nx4);

    cudaFuncSetAttribute(gemm_qkv, cudaFuncAttributeMaxDynamicSharedMemorySize, GSMEM);
    cudaFuncSetAttribute(gemm_mma, cudaFuncAttributeMaxDynamicSharedMemorySize, GSMEM);

    // fused QKV projection + rope/rmsnorm/gate epilogue
    gemm_qkv<<<dim3(12, M/128), 256, GSMEM>>>(xp, wp, x, ve, cosb, sinb, Wgate, S);

    // attention (tensor-core flash)
    cudaFuncSetAttribute(attn_kernel, cudaFuncAttributeMaxDynamicSharedMemorySize, ASMEM);
    attn_kernel<<<dim3(S/64, NH, B), 128, ASMEM>>>(amask, lw, S);

    // output projection straight into d_out
    gemm_mma<<<dim3(8, M/128), 256, GSMEM>>>(yp, wpp, out, 1024);
}

// round 7
// speedup vs baseline: 9.4008x; 1.1912x over previous
#include <cuda_runtime.h>
#include <cuda_fp16.h>
#include <math.h>
#include <stdint.h>

#define NE   1024
#define NH   16
#define NKV  4
#define HD   64
#define SMAX 2048
#define BMAX 2
#define MMAX (BMAX*SMAX)
#define RMS_EPS 1.1920929e-07f
#define SM_SHIFT 13.0f

// ---------------- scratch (device globals; no allocation allowed) ----------
__device__ __half g_x[(size_t)MMAX*NE];          // x fp16
__device__ __half g_w[1536*1024];                // fused Wq|Wk|Wv fp16
__device__ __half g_wp[1024*1024];               // Wproj fp16
__device__ __half g_y[(size_t)MMAX*NE];          // attention out fp16
__device__ __half g_q[(size_t)BMAX*NH*SMAX*HD];  // roped q (scale+log2e folded)
__device__ __half g_k[(size_t)BMAX*NKV*SMAX*HD];
__device__ __half g_v[(size_t)BMAX*NKV*SMAX*HD];

// ---------------- PTX helpers (family-generic only) -------------------------
__device__ __forceinline__ uint32_t smem_to_u32(const void* p) {
    uint32_t a;
    asm("{ .reg .u64 t; cvta.to.shared.u64 t, %1; cvt.u32.u64 %0, t; }" : "=r"(a) : "l"(p));
    return a;
}
__device__ __forceinline__ void ldsm_x4(uint32_t& r0, uint32_t& r1, uint32_t& r2,
                                        uint32_t& r3, uint32_t addr) {
    asm volatile("ldmatrix.sync.aligned.m8n8.x4.shared.b16 {%0,%1,%2,%3}, [%4];"
        : "=r"(r0), "=r"(r1), "=r"(r2), "=r"(r3) : "r"(addr));
}
__device__ __forceinline__ void ldsm_x4_t(uint32_t& r0, uint32_t& r1, uint32_t& r2,
                                          uint32_t& r3, uint32_t addr) {
    asm volatile("ldmatrix.sync.aligned.m8n8.x4.trans.shared.b16 {%0,%1,%2,%3}, [%4];"
        : "=r"(r0), "=r"(r1), "=r"(r2), "=r"(r3) : "r"(addr));
}
__device__ __forceinline__ void mma_f16(float* c, const uint32_t* a, const uint32_t* b) {
    asm volatile("mma.sync.aligned.m16n8k16.row.col.f32.f16.f16.f32 "
        "{%0,%1,%2,%3}, {%4,%5,%6,%7}, {%8,%9}, {%0,%1,%2,%3};"
        : "+f"(c[0]), "+f"(c[1]), "+f"(c[2]), "+f"(c[3])
        : "r"(a[0]), "r"(a[1]), "r"(a[2]), "r"(a[3]), "r"(b[0]), "r"(b[1]));
}
__device__ __forceinline__ void cp16(uint32_t dst, const void* src) {
    asm volatile("cp.async.cg.shared.global [%0], [%1], 16;" :: "r"(dst), "l"(src));
}
#define CP_COMMIT() asm volatile("cp.async.commit_group;" ::: "memory")
#define CP_WAIT(n)  asm volatile("cp.async.wait_group %0;" :: "n"(n) : "memory")

__device__ __forceinline__ uint32_t pack_h2(float x, float y) {
    __half2 h = __floats2half2_rn(x, y);
    return *(uint32_t*)&h;
}
__device__ __forceinline__ float ex2(float x) {
    float r; asm("ex2.approx.ftz.f32 %0, %1;" : "=f"(r) : "f"(x)); return r;
}

// ---------------- merged fp32 -> fp16 convert --------------------------------
// segments (float4 units): x (nx4), Wq (256K), Wk (64K), Wv (64K), Wproj (256K)
__global__ void __launch_bounds__(256) cvt_all(
    const float* __restrict__ x,  const float* __restrict__ Wq,
    const float* __restrict__ Wk, const float* __restrict__ Wv,
    const float* __restrict__ Wproj, __half* __restrict__ xo, int nx4)
{
    int i = blockIdx.x * 256 + threadIdx.x;
    const float* src;
    __half* h;
    int o;
    if (i < nx4) { src = x; h = xo; o = i; }
    else {
        i -= nx4;
        if      (i < 262144)  { src = Wq;    h = g_w;           o = i; }
        else if (i < 327680)  { src = Wk;    h = g_w + 1048576; o = i - 262144; }
        else if (i < 393216)  { src = Wv;    h = g_w + 1310720; o = i - 327680; }
        else if (i < 655360)  { src = Wproj; h = g_wp;          o = i - 393216; }
        else return;
    }
    float4 v = ((const float4*)src)[o];
    ((uint32_t*)h)[o*2]   = pack_h2(v.x, v.y);
    ((uint32_t*)h)[o*2+1] = pack_h2(v.z, v.w);
}

// ---------------- fp16 mma.sync GEMM mainloop --------------------------------
#define STG_BYTES 32768   /* A|B regions, 16KB each */
#define GSMEM (3*STG_BYTES)

__device__ __forceinline__ void gemm_issue_stage(
    uint32_t sbase, int stg, int kc,
    const __half* __restrict__ A, const __half* __restrict__ W,
    int bm, int bn, int K, int tid)
{
    #pragma unroll
    for (int i = 0; i < 8; i++) {
        const int idx = i * 256 + tid;           // 0..2047
        const int region = idx >> 10;            // 0:A 1:W
        const int cid = idx & 1023;
        const int row = cid >> 3, c16 = cid & 7;
        const uint32_t off = row * 128 + c16 * 16;
        const uint32_t sw = off ^ ((off >> 3) & 0x70);
        const int gk = kc * 64 + c16 * 8;
        const __half* src = region ? (W + (size_t)(bn + row) * K + gk)
                                   : (A + (size_t)(bm + row) * K + gk);
        cp16(sbase + stg * STG_BYTES + region * 16384 + sw, src);
    }
}

__device__ __forceinline__ void gemm_mainloop(
    float c[2][8][4], uint32_t sbase,
    const __half* A, const __half* W, int bm, int bn, int tid)
{
    constexpr int K = 1024;
    constexpr int NK = K / 64;
    const int wid = tid >> 5, lane = tid & 31;
    const int warpM = wid & 3, warpN = wid >> 2;
    const int rIn = lane & 7, mId = lane >> 3;

    #pragma unroll
    for (int mt = 0; mt < 2; mt++)
        #pragma unroll
        for (int n = 0; n < 8; n++)
            #pragma unroll
            for (int j = 0; j < 4; j++) c[mt][n][j] = 0.f;

    gemm_issue_stage(sbase, 0, 0, A, W, bm, bn, K, tid); CP_COMMIT();
    gemm_issue_stage(sbase, 1, 1, A, W, bm, bn, K, tid); CP_COMMIT();

    for (int kc = 0; kc < NK; kc++) {
        const int stg = kc % 3;
        if (kc + 2 < NK) {
            gemm_issue_stage(sbase, (kc + 2) % 3, kc + 2, A, W, bm, bn, K, tid);
            CP_COMMIT();
            CP_WAIT(2);
        } else if (kc + 1 < NK) {
            CP_WAIT(1);
        } else {
            CP_WAIT(0);
        }
        __syncthreads();

        const uint32_t aA = sbase + stg * STG_BYTES;
        const uint32_t aB = aA + 16384;

        #pragma unroll
        for (int kk = 0; kk < 64; kk += 16) {
            uint32_t a[2][4];
            #pragma unroll
            for (int mt = 0; mt < 2; mt++) {
                const int row = warpM * 32 + mt * 16 + (mId & 1) * 8 + rIn;
                const int colB = (kk + (mId >> 1) * 8) * 2;
                const uint32_t off = row * 128 + colB;
                const uint32_t sw = off ^ ((off >> 3) & 0x70);
                ldsm_x4(a[mt][0], a[mt][1], a[mt][2], a[mt][3], aA + sw);
            }
            uint32_t b[8][2];
            #pragma unroll
            for (int nt = 0; nt < 4; nt++) {
                const int row = warpN * 64 + nt * 16 + (mId >> 1) * 8 + rIn;
                const int colB = (kk + (mId & 1) * 8) * 2;
                const uint32_t off = row * 128 + colB;
                const uint32_t sw = off ^ ((off >> 3) & 0x70);
                ldsm_x4(b[2*nt][0], b[2*nt][1], b[2*nt+1][0], b[2*nt+1][1], aB + sw);
            }
            #pragma unroll
            for (int mt = 0; mt < 2; mt++)
                #pragma unroll
                for (int n = 0; n < 8; n++)
                    mma_f16(c[mt][n], a[mt], b[n]);
        }
        __syncthreads();
    }
}

// ---------------- proj GEMM (fp32 out) ---------------------------------------
__global__ void __launch_bounds__(256, 2) gemm_mma(
    const __half* __restrict__ A, const __half* __restrict__ W,
    float* __restrict__ C, int ldc)
{
    extern __shared__ char gsm[];
    const uint32_t sbase = smem_to_u32(gsm);
    const int tid = threadIdx.x, wid = tid >> 5, lane = tid & 31;
    const int warpM = wid & 3, warpN = wid >> 2;
    const int bm = blockIdx.y * 128, bn = blockIdx.x * 128;

    float c[2][8][4];
    gemm_mainloop(c, sbase, A, W, bm, bn, tid);

    const int g = lane >> 2, t = lane & 3;
    #pragma unroll
    for (int mt = 0; mt < 2; mt++) {
        #pragma unroll
        for (int n = 0; n < 8; n++) {
            const int r0 = bm + warpM * 32 + mt * 16 + g;
            const int col = bn + warpN * 64 + n * 8 + t * 2;
            *(float2*)&C[(size_t)r0 * ldc + col]       = make_float2(c[mt][n][0], c[mt][n][1]);
            *(float2*)&C[(size_t)(r0 + 8) * ldc + col] = make_float2(c[mt][n][2], c[mt][n][3]);
        }
    }
}

// ---------------- QKV GEMM with fused rope/rmsnorm/gate epilogue -------------
__global__ void __launch_bounds__(256, 2) gemm_qkv(
    const __half* __restrict__ A, const __half* __restrict__ W,
    const float* __restrict__ x, const float* __restrict__ ve,
    const float* __restrict__ cosb, const float* __restrict__ sinb,
    const float* __restrict__ Wgate, int S)
{
    extern __shared__ char gsm[];
    const uint32_t sbase = smem_to_u32(gsm);
    const int tid = threadIdx.x, wid = tid >> 5, lane = tid & 31;
    const int warpM = wid & 3, warpN = wid >> 2;
    const int bm = blockIdx.y * 128, bn = blockIdx.x * 128;

    float c[2][8][4];
    gemm_mainloop(c, sbase, A, W, bm, bn, tid);

    const int g = lane >> 2, t = lane & 3;
    const int colbase = bn + warpN * 64;
    const int type = (colbase < 1024) ? 0 : (colbase < 1280 ? 1 : 2);
    // q gets softmax scale and log2(e) folded in; k gets plain 1.2
    const float sQK = (type == 0) ? (1.2f * 0.125f * 1.44269504f) : 1.2f;

    #pragma unroll
    for (int mt = 0; mt < 2; mt++) {
        #pragma unroll
        for (int e = 0; e < 2; e++) {
            const int row = warpM * 32 + mt * 16 + g + e * 8;
            const int m = bm + row;
            const int b = m / S, s = m - b * S;
            if (type <= 1) {
                float r1[4][2], r2[4][2];
                float ss = 0.f;
                #pragma unroll
                for (int n = 0; n < 4; n++) {
                    const int d0 = n * 8 + 2 * t;
                    const float cs0 = cosb[s*32 + d0], cs1 = cosb[s*32 + d0 + 1];
                    const float sn0 = sinb[s*32 + d0], sn1 = sinb[s*32 + d0 + 1];
                    const float t1a = c[mt][n][2*e],   t1b = c[mt][n][2*e+1];
                    const float t2a = c[mt][n+4][2*e], t2b = c[mt][n+4][2*e+1];
                    r1[n][0] = t1a*cs0 + t2a*sn0;  r1[n][1] = t1b*cs1 + t2b*sn1;
                    r2[n][0] = t2a*cs0 - t1a*sn0;  r2[n][1] = t2b*cs1 - t1b*sn1;
                    ss += r1[n][0]*r1[n][0] + r1[n][1]*r1[n][1]
                        + r2[n][0]*r2[n][0] + r2[n][1]*r2[n][1];
                }
                ss += __shfl_xor_sync(0xffffffffu, ss, 1);
                ss += __shfl_xor_sync(0xffffffffu, ss, 2);
                const float inv = rsqrtf(ss * (1.0f/64.0f) + RMS_EPS) * sQK;
                __half* dst;
                size_t doff;
                if (type == 0) {
                    const int hh = colbase >> 6;
                    doff = ((size_t)(b*NH + hh)*S + s) * HD;
                    dst = g_q;
                } else {
                    const int kh = (colbase - 1024) >> 6;
                    doff = ((size_t)(b*NKV + kh)*S + s) * HD;
                    dst = g_k;
                }
                #pragma unroll
                for (int n = 0; n < 4; n++) {
                    const int d0 = n * 8 + 2 * t;
                    *(uint32_t*)(dst + doff + d0)      = pack_h2(r1[n][0]*inv, r1[n][1]*inv);
                    *(uint32_t*)(dst + doff + d0 + 32) = pack_h2(r2[n][0]*inv, r2[n][1]*inv);
                }
            } else {
                const int kvh = (colbase - 1280) >> 6;
                float gz = 0.f;
                #pragma unroll
                for (int j = 0; j < 3; j++)
                    gz += x[(size_t)m*NE + 3*t + j] * Wgate[kvh*12 + 3*t + j];
                gz += __shfl_xor_sync(0xffffffffu, gz, 1);
                gz += __shfl_xor_sync(0xffffffffu, gz, 2);
                const float gate = 3.0f / (1.0f + __expf(-gz));
                const size_t doff = ((size_t)(b*NKV + kvh)*S + s) * HD;
                const float* vep = ve + (size_t)m*256 + kvh*64;
                #pragma unroll
                for (int n = 0; n < 8; n++) {
                    const int d0 = n * 8 + 2 * t;
                    const float v0 = c[mt][n][2*e]   + gate * vep[d0];
                    const float v1 = c[mt][n][2*e+1] + gate * vep[d0+1];
                    *(uint32_t*)(g_v + doff + d0) = pack_h2(v0, v1);
                }
            }
        }
    }
}

// ---------------- flash attention, fixed-shift softmax (no running max) ------
// Scores arrive in log2 domain (log2e folded into q). |s| <= 16.62 by
// Cauchy-Schwarz on the rmsnormed q/k, so p = 2^(s-13) <= 12.3: no overflow,
// no running max, no rescaling, l reduced once at the end.
#define AOFF_Q   0
#define AOFF_STG 8192
#define ASTG_STRIDE 16640   /* K (8KB) + V (8KB) + amask (256B) */
#define ASMEM (AOFF_STG + 2*ASTG_STRIDE)

__device__ __forceinline__ void attn_issue_stage(
    uint32_t sbase, int buf,
    const __half* K, const __half* V, const int* amrow, int tid)
{
    const uint32_t stg = sbase + AOFF_STG + buf * ASTG_STRIDE;
    #pragma unroll
    for (int i = 0; i < 8; i++) {
        const int idx = i * 128 + tid;        // 0..1023
        const int region = idx >> 9;          // 0:K 1:V
        const int cid = idx & 511;
        const int row = cid >> 3, c16 = cid & 7;
        const uint32_t off = row * 128 + c16 * 16;
        const uint32_t sw = off ^ ((off >> 3) & 0x70);
        const __half* src = region ? (V + row * 64 + c16 * 8) : (K + row * 64 + c16 * 8);
        cp16(stg + region * 8192 + sw, src);
    }
    if (tid < 16) cp16(stg + 16384 + tid * 16, amrow + tid * 4);
}

__global__ void __launch_bounds__(128) attn_kernel(
    const int* __restrict__ amask, const int* __restrict__ lwp, int S)
{
    extern __shared__ char asm_[];
    const uint32_t sbase = smem_to_u32(asm_);
    const int q0 = blockIdx.x * 64;
    const int h  = blockIdx.y;
    const int bz = blockIdx.z;
    const int kvh = h >> 2;
    const int LW = *lwp;
    const int tid = threadIdx.x, warp = tid >> 5, lane = tid & 31;
    const int rIn = lane & 7, mId = lane >> 3;
    const int g = lane >> 2, t = lane & 3;

    const __half* Q0 = g_q + ((size_t)(bz*NH + h)*S + q0) * HD;
    const __half* K0 = g_k + ((size_t)(bz*NKV + kvh)*S) * HD;
    const __half* V0 = g_v + ((size_t)(bz*NKV + kvh)*S) * HD;
    const int* am0 = amask + bz * S;

    #pragma unroll
    for (int i = 0; i < 4; i++) {
        const int idx = i * 128 + tid;
        const int row = idx >> 3, c16 = idx & 7;
        const uint32_t off = row * 128 + c16 * 16;
        const uint32_t sw = off ^ ((off >> 3) & 0x70);
        *(uint4*)(asm_ + AOFF_Q + sw) = *(const uint4*)(Q0 + row * 64 + c16 * 8);
    }

    int kmin = q0 - LW + 1; if (kmin < 0) kmin = 0;
    const int kt0 = kmin >> 6, kt1 = q0 >> 6;
    const int nt = kt1 - kt0 + 1;

    attn_issue_stage(sbase, 0, K0 + (size_t)(kt0<<6)*HD, V0 + (size_t)(kt0<<6)*HD,
                     am0 + (kt0<<6), tid);
    CP_COMMIT();
    if (nt > 1) {
        attn_issue_stage(sbase, 1, K0 + (size_t)((kt0+1)<<6)*HD, V0 + (size_t)((kt0+1)<<6)*HD,
                         am0 + ((kt0+1)<<6), tid);
        CP_COMMIT();
    }

    __syncthreads();

    uint32_t aq[4][4];
    #pragma unroll
    for (int kk = 0; kk < 4; kk++) {
        const int row = warp * 16 + (mId & 1) * 8 + rIn;
        const int colB = (kk * 16 + (mId >> 1) * 8) * 2;
        const uint32_t off = row * 128 + colB;
        const uint32_t sw = off ^ ((off >> 3) & 0x70);
        ldsm_x4(aq[kk][0], aq[kk][1], aq[kk][2], aq[kk][3], sbase + AOFF_Q + sw);
    }

    float o[8][4];
    #pragma unroll
    for (int j = 0; j < 8; j++)
        #pragma unroll
        for (int e = 0; e < 4; e++) o[j][e] = 0.f;
    float l0 = 0.f, l1 = 0.f;          // per-thread partial softmax sums
    const int r0g = q0 + warp * 16 + g;
    const int r1g = r0g + 8;

    for (int i = 0; i < nt; i++) {
        const int kt = kt0 + i, buf = i & 1;
        const int k0 = kt << 6;
        if (i + 1 < nt) { CP_WAIT(1); } else { CP_WAIT(0); }
        __syncthreads();

        const uint32_t stg = sbase + AOFF_STG + buf * ASTG_STRIDE;
        const uint32_t sK = stg, sV = stg + 8192;
        const int* sAm = (const int*)(asm_ + AOFF_STG + buf * ASTG_STRIDE + 16384);

        float sc[8][4];
        #pragma unroll
        for (int j = 0; j < 8; j++)
            #pragma unroll
            for (int e = 0; e < 4; e++) sc[j][e] = 0.f;

        #pragma unroll
        for (int kk = 0; kk < 4; kk++) {
            uint32_t b[8][2];
            #pragma unroll
            for (int ntp = 0; ntp < 4; ntp++) {
                const int row = ntp * 16 + (mId >> 1) * 8 + rIn;
                const int colB = (kk * 16 + (mId & 1) * 8) * 2;
                const uint32_t off = row * 128 + colB;
                const uint32_t sw = off ^ ((off >> 3) & 0x70);
                ldsm_x4(b[2*ntp][0], b[2*ntp][1], b[2*ntp+1][0], b[2*ntp+1][1], sK + sw);
            }
            #pragma unroll
            for (int j = 0; j < 8; j++)
                mma_f16(sc[j], aq[kk], b[j]);
        }

        // fixed-shift softmax: p = 2^(s - SHIFT), masked -> 0. No max, no rescale.
        #pragma unroll
        for (int j = 0; j < 8; j++) {
            const int ce = 8*j + 2*t, co = ce + 1;
            const int ae = sAm[ce], ao = sAm[co];
            const int gce = k0 + ce, gco = k0 + co;
            const bool a0 = ((unsigned)(r0g - gce) < (unsigned)LW) && (ae != 0);
            const bool a1 = ((unsigned)(r0g - gco) < (unsigned)LW) && (ao != 0);
            const bool a2 = ((unsigned)(r1g - gce) < (unsigned)LW) && (ae != 0);
            const bool a3 = ((unsigned)(r1g - gco) < (unsigned)LW) && (ao != 0);
            const float p0 = a0 ? ex2(sc[j][0] - SM_SHIFT) : 0.f;
            const float p1 = a1 ? ex2(sc[j][1] - SM_SHIFT) : 0.f;
            const float p2 = a2 ? ex2(sc[j][2] - SM_SHIFT) : 0.f;
            const float p3 = a3 ? ex2(sc[j][3] - SM_SHIFT) : 0.f;
            sc[j][0] = p0; sc[j][1] = p1; sc[j][2] = p2; sc[j][3] = p3;
            l0 += p0 + p1; l1 += p2 + p3;
        }

        uint32_t pa[4][4];
        #pragma unroll
        for (int kb = 0; kb < 4; kb++) {
            const int j0 = 2*kb, j1 = 2*kb + 1;
            pa[kb][0] = pack_h2(sc[j0][0], sc[j0][1]);
            pa[kb][1] = pack_h2(sc[j0][2], sc[j0][3]);
            pa[kb][2] = pack_h2(sc[j1][0], sc[j1][1]);
            pa[kb][3] = pack_h2(sc[j1][2], sc[j1][3]);
        }

        #pragma unroll
        for (int kb = 0; kb < 4; kb++) {
            uint32_t v[8][2];
            #pragma unroll
            for (int dp = 0; dp < 4; dp++) {
                const int row = kb * 16 + (mId & 1) * 8 + rIn;
                const int colB = (dp * 16 + (mId >> 1) * 8) * 2;
                const uint32_t off = row * 128 + colB;
                const uint32_t sw = off ^ ((off >> 3) & 0x70);
                ldsm_x4_t(v[2*dp][0], v[2*dp][1], v[2*dp+1][0], v[2*dp+1][1], sV + sw);
            }
            #pragma unroll
            for (int j = 0; j < 8; j++)
                mma_f16(o[j], pa[kb], v[j]);
        }

        __syncthreads();
        if (i + 2 < nt) {
            const int kn = (kt + 2) << 6;
            attn_issue_stage(sbase, buf, K0 + (size_t)kn*HD, V0 + (size_t)kn*HD,
                             am0 + kn, tid);
            CP_COMMIT();
        }
    }

    // single end-of-kernel l reduction across the quad
    l0 += __shfl_xor_sync(0xffffffffu, l0, 1);
    l0 += __shfl_xor_sync(0xffffffffu, l0, 2);
    l1 += __shfl_xor_sync(0xffffffffu, l1, 1);
    l1 += __shfl_xor_sync(0xffffffffu, l1, 2);

    const float inv0 = 1.0f / l0, inv1 = 1.0f / l1;
    const size_t tok0 = (size_t)(bz*S + r0g) * NE + h*HD;
    const size_t tok1 = (size_t)(bz*S + r1g) * NE + h*HD;
    #pragma unroll
    for (int j = 0; j < 8; j++) {
        const int d0 = 8*j + 2*t;
        *(uint32_t*)(g_y + tok0 + d0) = pack_h2(o[j][0]*inv0, o[j][1]*inv0);
        *(uint32_t*)(g_y + tok1 + d0) = pack_h2(o[j][2]*inv1, o[j][3]*inv1);
    }
}

// ---------------- launch ----------------------------------------------------
extern "C" void kernel_launch(void* const* d_in, const int* in_sizes, int n_in,
                              void* d_out, int out_size)
{
    const float* x     = (const float*)d_in[0];
    const float* ve    = (const float*)d_in[1];
    const float* cosb  = (const float*)d_in[2];
    const float* sinb  = (const float*)d_in[3];
    const float* Wq    = (const float*)d_in[4];
    const float* Wk    = (const float*)d_in[5];
    const float* Wv    = (const float*)d_in[6];
    const float* Wproj = (const float*)d_in[7];
    const float* Wgate = (const float*)d_in[8];
    const int*   amask = (const int*)d_in[9];
    const int*   lw    = (const int*)d_in[10];
    float* out = (float*)d_out;

    const int S = in_sizes[2] / 32;        // cos is (S,1,32)
    const int B = in_sizes[0] / (S * NE);
    const int M = B * S;

    __half *xp, *wp, *wpp, *yp;
    cudaGetSymbolAddress((void**)&xp,  g_x);
    cudaGetSymbolAddress((void**)&wp,  g_w);
    cudaGetSymbolAddress((void**)&wpp, g_wp);
    cudaGetSymbolAddress((void**)&yp,  g_y);

    // merged fp32 -> fp16 converts
    const int nx4 = M * NE / 4;
    const int ntot = nx4 + 655360;
    cvt_all<<<(ntot + 255)/256, 256>>>(x, Wq, Wk, Wv, Wproj, xp, nx4);

    cudaFuncSetAttribute(gemm_qkv, cudaFuncAttributeMaxDynamicSharedMemorySize, GSMEM);
    cudaFuncSetAttribute(gemm_mma, cudaFuncAttributeMaxDynamicSharedMemorySize, GSMEM);

    // fused QKV projection + rope/rmsnorm/gate epilogue
    gemm_qkv<<<dim3(12, M/128), 256, GSMEM>>>(xp, wp, x, ve, cosb, sinb, Wgate, S);

    // attention (tensor-core flash, fixed-shift softmax)
    cudaFuncSetAttribute(attn_kernel, cudaFuncAttributeMaxDynamicSharedMemorySize, ASMEM);
    attn_kernel<<<dim3(S/64, NH, B), 128, ASMEM>>>(amask, lw, S);

    // output projection straight into d_out
    gemm_mma<<<dim3(8, M/128), 256, GSMEM>>>(yp, wpp, out, 1024);
}